// round 11
// baseline (speedup 1.0000x reference)
#include <cuda_runtime.h>
#include <cuda_fp16.h>
#include <math.h>
#include <stdint.h>

// ---------------------------------------------------------------------------
// Problem constants
// ---------------------------------------------------------------------------
#define Bb   32
#define Cc   128
#define Pp   128
#define Nn   (Bb * Pp)    // 4096 rows
#define Kk   510
#define KL   512
#define Zz   128
#define DS   256
#define HW   4096
#define EPSV 1e-5f
#define INV_NORM 0.08838834764831845f

#define KP   512
#define Ntot 16384        // 4*HW

// output layout
#define OFF_W   0
#define OFF_L   (Nn * KL)
#define OFF_LP  (2 * Nn * KL)
#define OFF_S   (3 * Nn * KL)

// GEMM tiling: CTA 128x128x64, 2-stage double buffer
#define TM 128
#define TN 128
#define TK 64                  // fp16 per k-chunk (128 B per row)
#define NCHUNK (KP / TK)       // 8
#define RPX 144                // row pitch bytes (128B data + 16B pad)
#define TILE_BYTES (128 * RPX) // 18432
#define STAGE_BYTES (2 * TILE_BYTES)
#define STAGES 2
#define SMEM_DYN (STAGES * STAGE_BYTES)   // 73728

// ---------------------------------------------------------------------------
// Device scratch (zero-initialized; rows k>=510 of g_spT stay zero)
// ---------------------------------------------------------------------------
__device__ __align__(16) float  g_lat[Kk * Zz];
__device__ __align__(16) __half g_wA [Nn * KP];            // 4.2 MB
__device__ __align__(16) __half g_spT[(size_t)Ntot * KP];  // 16.8 MB

// ---------------------------------------------------------------------------
// PTX helpers (sm_80-era; valid on plain compute_103 target)
// ---------------------------------------------------------------------------
__device__ __forceinline__ uint32_t smem_u32(const void* p) {
    uint32_t a;
    asm("{ .reg .u64 t; cvta.to.shared.u64 t, %1; cvt.u32.u64 %0, t; }"
        : "=r"(a) : "l"(p));
    return a;
}
#define CP_ASYNC16(dst, src) \
    asm volatile("cp.async.cg.shared.global [%0], [%1], 16;" :: "r"(dst), "l"(src))
#define CP_COMMIT() asm volatile("cp.async.commit_group;" ::: "memory")
#define CP_WAIT0()  asm volatile("cp.async.wait_group 0;" ::: "memory")

#define LDSM4(r0, r1, r2, r3, addr) \
    asm volatile("ldmatrix.sync.aligned.m8n8.x4.shared.b16 {%0,%1,%2,%3}, [%4];" \
        : "=r"(r0), "=r"(r1), "=r"(r2), "=r"(r3) : "r"(addr))

__device__ __forceinline__ void mma16816(float* c, const uint32_t* a,
                                         const uint32_t* b) {
    asm volatile(
        "mma.sync.aligned.m16n8k16.row.col.f32.f16.f16.f32 "
        "{%0,%1,%2,%3}, {%4,%5,%6,%7}, {%8,%9}, {%0,%1,%2,%3};"
        : "+f"(c[0]), "+f"(c[1]), "+f"(c[2]), "+f"(c[3])
        : "r"(a[0]), "r"(a[1]), "r"(a[2]), "r"(a[3]), "r"(b[0]), "r"(b[1]));
}

// ---------------------------------------------------------------------------
// R-row block reductions over 128 threads
// ---------------------------------------------------------------------------
template <int R>
__device__ __forceinline__ void redsumN(float v[R], float red[4][R], int t) {
    #pragma unroll
    for (int o = 16; o; o >>= 1)
        #pragma unroll
        for (int r = 0; r < R; r++) v[r] += __shfl_down_sync(0xffffffffu, v[r], o);
    if ((t & 31) == 0)
        #pragma unroll
        for (int r = 0; r < R; r++) red[t >> 5][r] = v[r];
    __syncthreads();
    #pragma unroll
    for (int r = 0; r < R; r++)
        v[r] = red[0][r] + red[1][r] + red[2][r] + red[3][r];
    __syncthreads();
}
template <int R>
__device__ __forceinline__ void redmaxN(float v[R], float red[4][R], int t) {
    #pragma unroll
    for (int o = 16; o; o >>= 1)
        #pragma unroll
        for (int r = 0; r < R; r++)
            v[r] = fmaxf(v[r], __shfl_down_sync(0xffffffffu, v[r], o));
    if ((t & 31) == 0)
        #pragma unroll
        for (int r = 0; r < R; r++) red[t >> 5][r] = v[r];
    __syncthreads();
    #pragma unroll
    for (int r = 0; r < R; r++)
        v[r] = fmaxf(fmaxf(red[0][r], red[1][r]), fmaxf(red[2][r], red[3][r]));
    __syncthreads();
}

// ---------------------------------------------------------------------------
// Shared-memory overlays for the fused kernel (k_lat | k_prep)
// ---------------------------------------------------------------------------
struct LatSh  { float lv[4][DS]; float red[4][4]; };
struct PrepSh { float tile[64][65]; };

// ---------------------------------------------------------------------------
// Fused launch 1: blocks [0,128) -> k_lat ; blocks [128, 128+2048) -> k_prep
// 128 threads per block.
// ---------------------------------------------------------------------------
__global__ void k_lat_prep(const float* __restrict__ latents,
                           const float* __restrict__ lw,
                           const float* __restrict__ lb,
                           const float* __restrict__ proto,
                           const float* __restrict__ masks) {
    __shared__ __align__(16) char shbuf[sizeof(LatSh) > sizeof(PrepSh)
                                        ? sizeof(LatSh) : sizeof(PrepSh)];
    int t = threadIdx.x;

    if (blockIdx.x < 128) {
        // ---- k_lat: 4 latents per block ----
        LatSh& sh = *(LatSh*)shbuf;
        int k0 = blockIdx.x * 4;

        #pragma unroll
        for (int r = 0; r < 4; r++) {
            int k = k0 + r;
            float a = 0.f, b2 = 0.f;
            if (k < Kk) { a = latents[k * DS + t]; b2 = latents[k * DS + t + 128]; }
            sh.lv[r][t] = a; sh.lv[r][t + 128] = b2;
        }
        __syncthreads();

        const float* wrow = lw + t * DS;
        float s[4] = {lb[t], lb[t], lb[t], lb[t]};
        #pragma unroll 4
        for (int d = 0; d < DS; d++) {
            float w = wrow[d];
            #pragma unroll
            for (int r = 0; r < 4; r++) s[r] += sh.lv[r][d] * w;
        }

        float v[4];
        #pragma unroll
        for (int r = 0; r < 4; r++) v[r] = s[r];
        redsumN<4>(v, sh.red, t);
        float d4[4];
        #pragma unroll
        for (int r = 0; r < 4; r++) {
            d4[r] = s[r] - v[r] * (1.f / 128.f);
            v[r] = d4[r] * d4[r];
        }
        redsumN<4>(v, sh.red, t);
        #pragma unroll
        for (int r = 0; r < 4; r++) {
            int k = k0 + r;
            if (k < Kk)
                g_lat[k * Zz + t] = d4[r] * rsqrtf(v[r] * (1.f / 128.f) + EPSV);
        }
    } else {
        // ---- k_prep: sprite^T fp16, 64x64 tile transpose ----
        PrepSh& sh = *(PrepSh*)shbuf;
        int bi = blockIdx.x - 128;         // 0..2047
        int n0 = (bi & 255) * 64;          // Ntot/64 = 256
        int k0 = (bi >> 8) * 64;           // KP/64 = 8

        for (int idx = t; idx < 4096; idx += 128) {
            int kk = idx >> 6, nn = idx & 63;
            int k = k0 + kk, n = n0 + nn;
            int ch = n >> 12, i = n & 4095;
            float s = 0.f;
            if (k < Kk)
                s = (ch < 3) ? proto[(size_t)k * (3 * HW) + ch * HW + i]
                             : masks[(size_t)k * HW + i];
            sh.tile[kk][nn] = s;
        }
        __syncthreads();

        for (int idx = t; idx < 4096; idx += 128) {
            int nn = idx >> 6, kk = idx & 63;
            if (k0 + kk < Kk)
                g_spT[(size_t)(n0 + nn) * KP + k0 + kk] =
                    __float2half(sh.tile[kk][nn]);
        }
    }
}

// ---------------------------------------------------------------------------
// Kernel 3: 8 rows per block (same p, 8 consecutive b)
// ---------------------------------------------------------------------------
__global__ void k_row(const float* __restrict__ x,
                      const float* __restrict__ blankl,
                      const float* __restrict__ aw,
                      const float* __restrict__ ab,
                      float* __restrict__ out) {
    int bi = blockIdx.x;          // 0..511
    int p  = bi & 127;
    int bq = bi >> 7;             // 0..3 -> b = bq*8 + r
    int t  = threadIdx.x;

    __shared__ float xv[8][Cc];
    __shared__ float av[8][Zz];
    __shared__ float lg[8][KL];
    __shared__ float red[4][8];

    #pragma unroll
    for (int r = 0; r < 8; r++)
        xv[r][t] = x[(size_t)(bq * 8 + r) * (Cc * Pp) + t * Pp + p];
    __syncthreads();

    // anchors linear + LN (8 rows)
    {
        const float* wrow = aw + t * Cc;
        float s[8];
        #pragma unroll
        for (int r = 0; r < 8; r++) s[r] = ab[t];
        #pragma unroll 4
        for (int c = 0; c < Cc; c++) {
            float w = wrow[c];
            #pragma unroll
            for (int r = 0; r < 8; r++) s[r] += xv[r][c] * w;
        }
        float v[8];
        #pragma unroll
        for (int r = 0; r < 8; r++) v[r] = s[r];
        redsumN<8>(v, red, t);
        float d8[8];
        #pragma unroll
        for (int r = 0; r < 8; r++) {
            d8[r] = s[r] - v[r] * (1.f / 128.f);
            v[r] = d8[r] * d8[r];
        }
        redsumN<8>(v, red, t);
        #pragma unroll
        for (int r = 0; r < 8; r++)
            av[r][t] = d8[r] * rsqrtf(v[r] * (1.f / 128.f) + EPSV);
    }

    // blank dots (8 rows)
    float lgb[8];
    {
        float bl = blankl[(p & 1) * Cc + t];
        float v[8];
        #pragma unroll
        for (int r = 0; r < 8; r++) v[r] = xv[r][t] * bl;
        redsumN<8>(v, red, t);
        #pragma unroll
        for (int r = 0; r < 8; r++) lgb[r] = v[r] * INV_NORM;
    }
    __syncthreads();   // av visible

    // logits: thread handles k = t + 128*j for all 8 rows
    #pragma unroll
    for (int j = 0; j < 4; j++) {
        int k = t + (j << 7);
        if (k < Kk) {
            const float4* lr = (const float4*)(g_lat + k * Zz);
            float acc[8] = {0.f, 0.f, 0.f, 0.f, 0.f, 0.f, 0.f, 0.f};
            #pragma unroll 4
            for (int i = 0; i < 32; i++) {
                float4 q = lr[i];
                #pragma unroll
                for (int r = 0; r < 8; r++)
                    acc[r] += q.x * av[r][4 * i]     + q.y * av[r][4 * i + 1]
                            + q.z * av[r][4 * i + 2] + q.w * av[r][4 * i + 3];
            }
            #pragma unroll
            for (int r = 0; r < 8; r++) lg[r][k] = acc[r] * INV_NORM;
        } else {
            #pragma unroll
            for (int r = 0; r < 8; r++) lg[r][k] = lgb[r];
        }
    }
    __syncthreads();

    // softmax over 512, 8 rows
    float v[8];
    #pragma unroll
    for (int r = 0; r < 8; r++) {
        float m = -1e30f;
        #pragma unroll
        for (int j = 0; j < 4; j++) m = fmaxf(m, lg[r][t + (j << 7)]);
        v[r] = m;
    }
    redmaxN<8>(v, red, t);
    float mx[8];
    #pragma unroll
    for (int r = 0; r < 8; r++) mx[r] = v[r];

    float ev[8][4];
    #pragma unroll
    for (int r = 0; r < 8; r++) {
        float s = 0.f;
        #pragma unroll
        for (int j = 0; j < 4; j++) {
            ev[r][j] = expf(lg[r][t + (j << 7)] - mx[r]);
            s += ev[r][j];
        }
        v[r] = s;
    }
    redsumN<8>(v, red, t);

    #pragma unroll
    for (int r = 0; r < 8; r++) {
        int b = bq * 8 + r;
        int n = (b << 7) + p;
        int m = (p << 5) + b;
        float inv_sum = 1.0f / v[r];
        float lse = mx[r] + logf(v[r]);
        float* out_w  = out + OFF_W  + (size_t)n * KL;
        float* out_l  = out + OFF_L  + (size_t)n * KL;
        float* out_lp = out + OFF_LP + (size_t)m * KL;
        __half* wa = g_wA + (size_t)m * KP;
        #pragma unroll
        for (int j = 0; j < 4; j++) {
            int k = t + (j << 7);
            float l = lg[r][k];
            float w = ev[r][j] * inv_sum;
            out_w[k]  = w;
            out_l[k]  = l;
            out_lp[k] = l - lse;
            wa[k] = __float2half(w);
        }
    }
}

// ---------------------------------------------------------------------------
// Kernel 4: mma.sync fp16 GEMM  C[4096,16384] = A[4096,512] @ B[16384,512]^T
// CTA 128x128x64, 8 warps, 2-stage double buffer, 2 CTAs/SM
// ---------------------------------------------------------------------------
__global__ void __launch_bounds__(256, 2) k_gemm(float* __restrict__ outS) {
    extern __shared__ __align__(128) char sm[];   // STAGES x [A|B]

    int t = threadIdx.x;
    int lane = t & 31;
    int wid = t >> 5;
    int warp_m = wid & 3;          // 32-row slice
    int warp_n = wid >> 2;         // 64-col slice
    int n0 = blockIdx.x * TN;
    int m0 = blockIdx.y * TM;

    uint32_t smb = smem_u32(sm);

    // cp.async mapping: thread t -> row t>>1, byte offset (t&1)*64, 4 x 16B
    int qr = t >> 1;
    int qo = (t & 1) * 64;

    const char* gA = (const char*)g_wA  + (size_t)(m0 + qr) * (KP * 2) + qo;
    const char* gB = (const char*)g_spT + (size_t)(n0 + qr) * (KP * 2) + qo;

    uint32_t sA = smb + qr * RPX + qo;
    uint32_t sB = sA + TILE_BYTES;

    uint32_t lmA = smb + (warp_m * 32 + (lane & 15)) * RPX + (lane >> 4) * 16;
    uint32_t lmB = smb + TILE_BYTES
                 + (warp_n * 64 + (lane & 7) + ((lane >> 4) & 1) * 8) * RPX
                 + ((lane >> 3) & 1) * 16;

    float acc[2][8][4];
    #pragma unroll
    for (int mt = 0; mt < 2; mt++)
        #pragma unroll
        for (int nt = 0; nt < 8; nt++)
            #pragma unroll
            for (int q = 0; q < 4; q++) acc[mt][nt][q] = 0.f;

    // prefetch chunk 0 -> stage 0
    #pragma unroll
    for (int i = 0; i < 4; i++) {
        CP_ASYNC16(sA + i * 16, gA + i * 16);
        CP_ASYNC16(sB + i * 16, gB + i * 16);
    }
    CP_COMMIT();

    for (int c = 0; c < NCHUNK; c++) {
        CP_WAIT0();            // chunk c landed
        __syncthreads();       // all warps done computing c-1 -> other stage free

        if (c + 1 < NCHUNK) {  // issue chunk c+1 into the other stage
            uint32_t so = ((c + 1) & 1) * STAGE_BYTES;
            int cb = (c + 1) * 128;       // 128 B per K-chunk
            #pragma unroll
            for (int i = 0; i < 4; i++) {
                CP_ASYNC16(sA + so + i * 16, gA + cb + i * 16);
                CP_ASYNC16(sB + so + i * 16, gB + cb + i * 16);
            }
            CP_COMMIT();
        }

        uint32_t aoff = lmA + (c & 1) * STAGE_BYTES;
        uint32_t boff = lmB + (c & 1) * STAGE_BYTES;
        #pragma unroll
        for (int kt = 0; kt < 4; kt++) {
            uint32_t a[2][4];
            #pragma unroll
            for (int mt = 0; mt < 2; mt++)
                LDSM4(a[mt][0], a[mt][1], a[mt][2], a[mt][3],
                      aoff + mt * (16 * RPX) + kt * 32);
            uint32_t bfr[8][2];
            #pragma unroll
            for (int pg = 0; pg < 4; pg++)
                LDSM4(bfr[2 * pg][0], bfr[2 * pg][1],
                      bfr[2 * pg + 1][0], bfr[2 * pg + 1][1],
                      boff + pg * (16 * RPX) + kt * 32);
            #pragma unroll
            for (int mt = 0; mt < 2; mt++)
                #pragma unroll
                for (int nt = 0; nt < 8; nt++)
                    mma16816(acc[mt][nt], a[mt], bfr[nt]);
        }
    }

    // epilogue
    int rbase = m0 + warp_m * 32 + (lane >> 2);
    int cbase = n0 + warp_n * 64 + (lane & 3) * 2;
    #pragma unroll
    for (int mt = 0; mt < 2; mt++) {
        #pragma unroll
        for (int nt = 0; nt < 8; nt++) {
            int r = rbase + mt * 16;
            int cc = cbase + nt * 8;
            *(float2*)(outS + (size_t)r * Ntot + cc) =
                make_float2(acc[mt][nt][0], acc[mt][nt][1]);
            *(float2*)(outS + (size_t)(r + 8) * Ntot + cc) =
                make_float2(acc[mt][nt][2], acc[mt][nt][3]);
        }
    }
}

// ---------------------------------------------------------------------------
// Launch
// ---------------------------------------------------------------------------
extern "C" void kernel_launch(void* const* d_in, const int* in_sizes, int n_in,
                              void* d_out, int out_size) {
    const float* x       = (const float*)d_in[0];
    const float* latents = (const float*)d_in[1];
    const float* blankl  = (const float*)d_in[2];
    const float* lw      = (const float*)d_in[3];
    const float* lb      = (const float*)d_in[4];
    const float* aw      = (const float*)d_in[5];
    const float* ab      = (const float*)d_in[6];
    const float* proto   = (const float*)d_in[7];
    const float* masks   = (const float*)d_in[8];
    float* out = (float*)d_out;

    static int smem_set = 0;
    if (!smem_set) {
        cudaFuncSetAttribute(k_gemm, cudaFuncAttributeMaxDynamicSharedMemorySize,
                             SMEM_DYN);
        smem_set = 1;
    }

    // launch 1: k_lat (blocks 0..127) || k_prep (blocks 128..2175)
    k_lat_prep<<<128 + 2048, 128>>>(latents, lw, lb, proto, masks);
    // launch 2: per-row softmax pipeline (needs g_lat)
    k_row<<<512, 128>>>(x, blankl, aw, ab, out);
    // launch 3: tensor-core GEMM (needs g_wA, g_spT)
    dim3 gg(Ntot / TN, Nn / TM);
    k_gemm<<<gg, 256, SMEM_DYN>>>(out + OFF_S);
}

// round 12
// speedup vs baseline: 1.1746x; 1.1746x over previous
#include <cuda_runtime.h>
#include <cuda_fp16.h>
#include <math.h>
#include <stdint.h>

// ---------------------------------------------------------------------------
// Problem constants
// ---------------------------------------------------------------------------
#define Bb   32
#define Cc   128
#define Pp   128
#define Nn   (Bb * Pp)    // 4096 rows
#define Kk   510
#define KL   512
#define Zz   128
#define DS   256
#define HW   4096
#define EPSV 1e-5f
#define INV_NORM 0.08838834764831845f

#define KP   512
#define Ntot 16384        // 4*HW

// output layout
#define OFF_W   0
#define OFF_L   (Nn * KL)
#define OFF_LP  (2 * Nn * KL)
#define OFF_S   (3 * Nn * KL)

// GEMM tiling: CTA 128x128x32, 4-stage cp.async pipeline (round-10 proven +1)
#define TM 128
#define TN 128
#define TK 32                 // fp16 per k-chunk (64 B per row)
#define NCHUNK (KP / TK)      // 16
#define RP 80                 // smem row pitch (64B data + 16B pad)
#define TILE_BYTES (128 * RP) // 10240
#define STAGE_BYTES (2 * TILE_BYTES)
#define STAGES 4
#define SMEM_DYN (STAGES * STAGE_BYTES)   // 81920

// ---------------------------------------------------------------------------
// Device scratch (zero-initialized; rows k>=510 of g_spT stay zero)
// ---------------------------------------------------------------------------
__device__ __align__(16) float  g_lat[Kk * Zz];
__device__ __align__(16) __half g_wA [Nn * KP];            // 4.2 MB
__device__ __align__(16) __half g_spT[(size_t)Ntot * KP];  // 16.8 MB

// ---------------------------------------------------------------------------
// PTX helpers (sm_80-era; valid on plain compute_103 target)
// ---------------------------------------------------------------------------
__device__ __forceinline__ uint32_t smem_u32(const void* p) {
    uint32_t a;
    asm("{ .reg .u64 t; cvta.to.shared.u64 t, %1; cvt.u32.u64 %0, t; }"
        : "=r"(a) : "l"(p));
    return a;
}
#define CP_ASYNC16(dst, src) \
    asm volatile("cp.async.cg.shared.global [%0], [%1], 16;" :: "r"(dst), "l"(src))
#define CP_COMMIT() asm volatile("cp.async.commit_group;" ::: "memory")
#define CP_WAIT2()  asm volatile("cp.async.wait_group 2;" ::: "memory")

#define LDSM4(r0, r1, r2, r3, addr) \
    asm volatile("ldmatrix.sync.aligned.m8n8.x4.shared.b16 {%0,%1,%2,%3}, [%4];" \
        : "=r"(r0), "=r"(r1), "=r"(r2), "=r"(r3) : "r"(addr))

__device__ __forceinline__ void mma16816(float* c, const uint32_t* a,
                                         const uint32_t* b) {
    asm volatile(
        "mma.sync.aligned.m16n8k16.row.col.f32.f16.f16.f32 "
        "{%0,%1,%2,%3}, {%4,%5,%6,%7}, {%8,%9}, {%0,%1,%2,%3};"
        : "+f"(c[0]), "+f"(c[1]), "+f"(c[2]), "+f"(c[3])
        : "r"(a[0]), "r"(a[1]), "r"(a[2]), "r"(a[3]), "r"(b[0]), "r"(b[1]));
}

// ---------------------------------------------------------------------------
// R-row block reductions over 128 threads
// ---------------------------------------------------------------------------
template <int R>
__device__ __forceinline__ void redsumN(float v[R], float red[4][R], int t) {
    #pragma unroll
    for (int o = 16; o; o >>= 1)
        #pragma unroll
        for (int r = 0; r < R; r++) v[r] += __shfl_down_sync(0xffffffffu, v[r], o);
    if ((t & 31) == 0)
        #pragma unroll
        for (int r = 0; r < R; r++) red[t >> 5][r] = v[r];
    __syncthreads();
    #pragma unroll
    for (int r = 0; r < R; r++)
        v[r] = red[0][r] + red[1][r] + red[2][r] + red[3][r];
    __syncthreads();
}
template <int R>
__device__ __forceinline__ void redmaxN(float v[R], float red[4][R], int t) {
    #pragma unroll
    for (int o = 16; o; o >>= 1)
        #pragma unroll
        for (int r = 0; r < R; r++)
            v[r] = fmaxf(v[r], __shfl_down_sync(0xffffffffu, v[r], o));
    if ((t & 31) == 0)
        #pragma unroll
        for (int r = 0; r < R; r++) red[t >> 5][r] = v[r];
    __syncthreads();
    #pragma unroll
    for (int r = 0; r < R; r++)
        v[r] = fmaxf(fmaxf(red[0][r], red[1][r]), fmaxf(red[2][r], red[3][r]));
    __syncthreads();
}

// ---------------------------------------------------------------------------
// Shared-memory overlays for the fused kernel (k_lat | k_prep)
// ---------------------------------------------------------------------------
struct LatSh  { float lv[4][DS]; float red[4][4]; };
struct PrepSh { float tile[64][65]; };

// ---------------------------------------------------------------------------
// Fused launch 1: blocks [0,128) -> k_lat ; blocks [128, 128+2048) -> k_prep
// ---------------------------------------------------------------------------
__global__ void k_lat_prep(const float* __restrict__ latents,
                           const float* __restrict__ lw,
                           const float* __restrict__ lb,
                           const float* __restrict__ proto,
                           const float* __restrict__ masks) {
    __shared__ __align__(16) char shbuf[sizeof(LatSh) > sizeof(PrepSh)
                                        ? sizeof(LatSh) : sizeof(PrepSh)];
    int t = threadIdx.x;

    if (blockIdx.x < 128) {
        LatSh& sh = *(LatSh*)shbuf;
        int k0 = blockIdx.x * 4;

        #pragma unroll
        for (int r = 0; r < 4; r++) {
            int k = k0 + r;
            float a = 0.f, b2 = 0.f;
            if (k < Kk) { a = latents[k * DS + t]; b2 = latents[k * DS + t + 128]; }
            sh.lv[r][t] = a; sh.lv[r][t + 128] = b2;
        }
        __syncthreads();

        const float* wrow = lw + t * DS;
        float s[4] = {lb[t], lb[t], lb[t], lb[t]};
        #pragma unroll 4
        for (int d = 0; d < DS; d++) {
            float w = wrow[d];
            #pragma unroll
            for (int r = 0; r < 4; r++) s[r] += sh.lv[r][d] * w;
        }

        float v[4];
        #pragma unroll
        for (int r = 0; r < 4; r++) v[r] = s[r];
        redsumN<4>(v, sh.red, t);
        float d4[4];
        #pragma unroll
        for (int r = 0; r < 4; r++) {
            d4[r] = s[r] - v[r] * (1.f / 128.f);
            v[r] = d4[r] * d4[r];
        }
        redsumN<4>(v, sh.red, t);
        #pragma unroll
        for (int r = 0; r < 4; r++) {
            int k = k0 + r;
            if (k < Kk)
                g_lat[k * Zz + t] = d4[r] * rsqrtf(v[r] * (1.f / 128.f) + EPSV);
        }
    } else {
        PrepSh& sh = *(PrepSh*)shbuf;
        int bi = blockIdx.x - 128;         // 0..2047
        int n0 = (bi & 255) * 64;          // Ntot/64 = 256
        int k0 = (bi >> 8) * 64;           // KP/64 = 8

        for (int idx = t; idx < 4096; idx += 128) {
            int kk = idx >> 6, nn = idx & 63;
            int k = k0 + kk, n = n0 + nn;
            int ch = n >> 12, i = n & 4095;
            float s = 0.f;
            if (k < Kk)
                s = (ch < 3) ? proto[(size_t)k * (3 * HW) + ch * HW + i]
                             : masks[(size_t)k * HW + i];
            sh.tile[kk][nn] = s;
        }
        __syncthreads();

        for (int idx = t; idx < 4096; idx += 128) {
            int nn = idx >> 6, kk = idx & 63;
            if (k0 + kk < Kk)
                g_spT[(size_t)(n0 + nn) * KP + k0 + kk] =
                    __float2half(sh.tile[kk][nn]);
        }
    }
}

// ---------------------------------------------------------------------------
// Kernel 3: 8 rows per block (same p, 8 consecutive b)
// ---------------------------------------------------------------------------
__global__ void k_row(const float* __restrict__ x,
                      const float* __restrict__ blankl,
                      const float* __restrict__ aw,
                      const float* __restrict__ ab,
                      float* __restrict__ out) {
    int bi = blockIdx.x;          // 0..511
    int p  = bi & 127;
    int bq = bi >> 7;             // 0..3 -> b = bq*8 + r
    int t  = threadIdx.x;

    __shared__ float xv[8][Cc];
    __shared__ float av[8][Zz];
    __shared__ float lg[8][KL];
    __shared__ float red[4][8];

    #pragma unroll
    for (int r = 0; r < 8; r++)
        xv[r][t] = x[(size_t)(bq * 8 + r) * (Cc * Pp) + t * Pp + p];
    __syncthreads();

    // anchors linear + LN (8 rows)
    {
        const float* wrow = aw + t * Cc;
        float s[8];
        #pragma unroll
        for (int r = 0; r < 8; r++) s[r] = ab[t];
        #pragma unroll 4
        for (int c = 0; c < Cc; c++) {
            float w = wrow[c];
            #pragma unroll
            for (int r = 0; r < 8; r++) s[r] += xv[r][c] * w;
        }
        float v[8];
        #pragma unroll
        for (int r = 0; r < 8; r++) v[r] = s[r];
        redsumN<8>(v, red, t);
        float d8[8];
        #pragma unroll
        for (int r = 0; r < 8; r++) {
            d8[r] = s[r] - v[r] * (1.f / 128.f);
            v[r] = d8[r] * d8[r];
        }
        redsumN<8>(v, red, t);
        #pragma unroll
        for (int r = 0; r < 8; r++)
            av[r][t] = d8[r] * rsqrtf(v[r] * (1.f / 128.f) + EPSV);
    }

    // blank dots (8 rows)
    float lgb[8];
    {
        float bl = blankl[(p & 1) * Cc + t];
        float v[8];
        #pragma unroll
        for (int r = 0; r < 8; r++) v[r] = xv[r][t] * bl;
        redsumN<8>(v, red, t);
        #pragma unroll
        for (int r = 0; r < 8; r++) lgb[r] = v[r] * INV_NORM;
    }
    __syncthreads();   // av visible

    // logits: thread handles k = t + 128*j for all 8 rows
    #pragma unroll
    for (int j = 0; j < 4; j++) {
        int k = t + (j << 7);
        if (k < Kk) {
            const float4* lr = (const float4*)(g_lat + k * Zz);
            float acc[8] = {0.f, 0.f, 0.f, 0.f, 0.f, 0.f, 0.f, 0.f};
            #pragma unroll 4
            for (int i = 0; i < 32; i++) {
                float4 q = lr[i];
                #pragma unroll
                for (int r = 0; r < 8; r++)
                    acc[r] += q.x * av[r][4 * i]     + q.y * av[r][4 * i + 1]
                            + q.z * av[r][4 * i + 2] + q.w * av[r][4 * i + 3];
            }
            #pragma unroll
            for (int r = 0; r < 8; r++) lg[r][k] = acc[r] * INV_NORM;
        } else {
            #pragma unroll
            for (int r = 0; r < 8; r++) lg[r][k] = lgb[r];
        }
    }
    __syncthreads();

    // softmax over 512, 8 rows
    float v[8];
    #pragma unroll
    for (int r = 0; r < 8; r++) {
        float m = -1e30f;
        #pragma unroll
        for (int j = 0; j < 4; j++) m = fmaxf(m, lg[r][t + (j << 7)]);
        v[r] = m;
    }
    redmaxN<8>(v, red, t);
    float mx[8];
    #pragma unroll
    for (int r = 0; r < 8; r++) mx[r] = v[r];

    float ev[8][4];
    #pragma unroll
    for (int r = 0; r < 8; r++) {
        float s = 0.f;
        #pragma unroll
        for (int j = 0; j < 4; j++) {
            ev[r][j] = expf(lg[r][t + (j << 7)] - mx[r]);
            s += ev[r][j];
        }
        v[r] = s;
    }
    redsumN<8>(v, red, t);

    #pragma unroll
    for (int r = 0; r < 8; r++) {
        int b = bq * 8 + r;
        int n = (b << 7) + p;
        int m = (p << 5) + b;
        float inv_sum = 1.0f / v[r];
        float lse = mx[r] + logf(v[r]);
        float* out_w  = out + OFF_W  + (size_t)n * KL;
        float* out_l  = out + OFF_L  + (size_t)n * KL;
        float* out_lp = out + OFF_LP + (size_t)m * KL;
        __half* wa = g_wA + (size_t)m * KP;
        #pragma unroll
        for (int j = 0; j < 4; j++) {
            int k = t + (j << 7);
            float l = lg[r][k];
            float w = ev[r][j] * inv_sum;
            out_w[k]  = w;
            out_l[k]  = l;
            out_lp[k] = l - lse;
            wa[k] = __float2half(w);
        }
    }
}

// ---------------------------------------------------------------------------
// Kernel 4: mma.sync fp16 GEMM  C[4096,16384] = A[4096,512] @ B[16384,512]^T
// CTA 128x128x32, 8 warps, 4-stage cp.async pipeline, 2 CTAs/SM
// ---------------------------------------------------------------------------
__global__ void __launch_bounds__(256, 2) k_gemm(float* __restrict__ outS) {
    extern __shared__ __align__(128) char sm[];   // STAGES x [A|B]

    int t = threadIdx.x;
    int lane = t & 31;
    int wid = t >> 5;
    int warp_m = wid & 3;          // 32-row slice
    int warp_n = wid >> 2;         // 64-col slice
    int n0 = blockIdx.x * TN;
    int m0 = blockIdx.y * TM;

    uint32_t smb = smem_u32(sm);

    // cp.async mapping: thread covers rows qr0 and qr0+64, 16B chunk qc
    int qr0 = t >> 2, qc = t & 3;
    int qr1 = qr0 + 64;

    const char* gA0 = (const char*)g_wA  + (size_t)(m0 + qr0) * (KP * 2) + qc * 16;
    const char* gA1 = (const char*)g_wA  + (size_t)(m0 + qr1) * (KP * 2) + qc * 16;
    const char* gB0 = (const char*)g_spT + (size_t)(n0 + qr0) * (KP * 2) + qc * 16;
    const char* gB1 = (const char*)g_spT + (size_t)(n0 + qr1) * (KP * 2) + qc * 16;

    uint32_t sA0 = smb + qr0 * RP + qc * 16;
    uint32_t sA1 = smb + qr1 * RP + qc * 16;
    uint32_t sB0 = sA0 + TILE_BYTES;
    uint32_t sB1 = sA1 + TILE_BYTES;

    uint32_t lmA = smb + (warp_m * 32 + (lane & 15)) * RP + (lane >> 4) * 16;
    uint32_t lmB = smb + TILE_BYTES
                 + (warp_n * 64 + (lane & 7) + ((lane >> 4) & 1) * 8) * RP
                 + ((lane >> 3) & 1) * 16;

    float acc[2][8][4];
    #pragma unroll
    for (int mt = 0; mt < 2; mt++)
        #pragma unroll
        for (int nt = 0; nt < 8; nt++)
            #pragma unroll
            for (int q = 0; q < 4; q++) acc[mt][nt][q] = 0.f;

    // prefetch chunks 0..2 into stages 0..2
    #pragma unroll
    for (int s = 0; s < STAGES - 1; s++) {
        uint32_t so = s * STAGE_BYTES;
        int cb = s * 64;
        CP_ASYNC16(sA0 + so, gA0 + cb);
        CP_ASYNC16(sA1 + so, gA1 + cb);
        CP_ASYNC16(sB0 + so, gB0 + cb);
        CP_ASYNC16(sB1 + so, gB1 + cb);
        CP_COMMIT();
    }

    for (int c = 0; c < NCHUNK; c++) {
        CP_WAIT2();            // chunk c landed (c+1, c+2 may be in flight)
        __syncthreads();       // all warps past compute of c-1 -> stage reuse safe

        // issue chunk c+3 into stage (c+3)%STAGES; always commit (group count)
        int cn = c + STAGES - 1;
        if (cn < NCHUNK) {
            uint32_t so = (cn % STAGES) * STAGE_BYTES;
            int cb = cn * 64;
            CP_ASYNC16(sA0 + so, gA0 + cb);
            CP_ASYNC16(sA1 + so, gA1 + cb);
            CP_ASYNC16(sB0 + so, gB0 + cb);
            CP_ASYNC16(sB1 + so, gB1 + cb);
        }
        CP_COMMIT();

        uint32_t aoff = lmA + (c % STAGES) * STAGE_BYTES;
        uint32_t boff = lmB + (c % STAGES) * STAGE_BYTES;
        #pragma unroll
        for (int kt = 0; kt < 2; kt++) {
            uint32_t a[2][4];
            #pragma unroll
            for (int mt = 0; mt < 2; mt++)
                LDSM4(a[mt][0], a[mt][1], a[mt][2], a[mt][3],
                      aoff + mt * (16 * RP) + kt * 32);
            uint32_t bfr[8][2];
            #pragma unroll
            for (int pg = 0; pg < 4; pg++)
                LDSM4(bfr[2 * pg][0], bfr[2 * pg][1],
                      bfr[2 * pg + 1][0], bfr[2 * pg + 1][1],
                      boff + pg * (16 * RP) + kt * 32);
            #pragma unroll
            for (int mt = 0; mt < 2; mt++)
                #pragma unroll
                for (int nt = 0; nt < 8; nt++)
                    mma16816(acc[mt][nt], a[mt], bfr[nt]);
        }
    }

    // epilogue
    int rbase = m0 + warp_m * 32 + (lane >> 2);
    int cbase = n0 + warp_n * 64 + (lane & 3) * 2;
    #pragma unroll
    for (int mt = 0; mt < 2; mt++) {
        #pragma unroll
        for (int nt = 0; nt < 8; nt++) {
            int r = rbase + mt * 16;
            int cc = cbase + nt * 8;
            *(float2*)(outS + (size_t)r * Ntot + cc) =
                make_float2(acc[mt][nt][0], acc[mt][nt][1]);
            *(float2*)(outS + (size_t)(r + 8) * Ntot + cc) =
                make_float2(acc[mt][nt][2], acc[mt][nt][3]);
        }
    }
}

// ---------------------------------------------------------------------------
// Launch
// ---------------------------------------------------------------------------
extern "C" void kernel_launch(void* const* d_in, const int* in_sizes, int n_in,
                              void* d_out, int out_size) {
    const float* x       = (const float*)d_in[0];
    const float* latents = (const float*)d_in[1];
    const float* blankl  = (const float*)d_in[2];
    const float* lw      = (const float*)d_in[3];
    const float* lb      = (const float*)d_in[4];
    const float* aw      = (const float*)d_in[5];
    const float* ab      = (const float*)d_in[6];
    const float* proto   = (const float*)d_in[7];
    const float* masks   = (const float*)d_in[8];
    float* out = (float*)d_out;

    static int smem_set = 0;
    if (!smem_set) {
        cudaFuncSetAttribute(k_gemm, cudaFuncAttributeMaxDynamicSharedMemorySize,
                             SMEM_DYN);
        smem_set = 1;
    }

    // launch 1: k_lat (blocks 0..127) || k_prep (blocks 128..2175)
    k_lat_prep<<<128 + 2048, 128>>>(latents, lw, lb, proto, masks);
    // launch 2: per-row softmax pipeline (needs g_lat)
    k_row<<<512, 128>>>(x, blankl, aw, ab, out);
    // launch 3: tensor-core GEMM (needs g_wA, g_spT)
    dim3 gg(Ntot / TN, Nn / TM);
    k_gemm<<<gg, 256, SMEM_DYN>>>(out + OFF_S);
}

// round 13
// speedup vs baseline: 1.1947x; 1.0171x over previous
#include <cuda_runtime.h>
#include <cuda_fp16.h>
#include <math.h>
#include <stdint.h>

// ---------------------------------------------------------------------------
// Problem constants
// ---------------------------------------------------------------------------
#define Bb   32
#define Cc   128
#define Pp   128
#define Nn   (Bb * Pp)    // 4096 rows
#define Kk   510
#define KL   512
#define Zz   128
#define DS   256
#define HW   4096
#define EPSV 1e-5f
#define INV_NORM 0.08838834764831845f

#define KP   512
#define Ntot 16384        // 4*HW

// output layout
#define OFF_W   0
#define OFF_L   (Nn * KL)
#define OFF_LP  (2 * Nn * KL)
#define OFF_S   (3 * Nn * KL)

// GEMM tiling: CTA 128x128x32, 3-stage cp.async pipeline (round-10 proven)
#define TM 128
#define TN 128
#define TK 32                 // fp16 per k-chunk (64 B per row)
#define NCHUNK (KP / TK)      // 16
#define RP 80                 // smem row pitch (64B data + 16B pad)
#define TILE_BYTES (128 * RP) // 10240
#define STAGE_BYTES (2 * TILE_BYTES)
#define STAGES 3
#define SMEM_DYN (STAGES * STAGE_BYTES)   // 61440

// ---------------------------------------------------------------------------
// Device scratch (zero-initialized; rows k>=510 of g_spT stay zero)
// ---------------------------------------------------------------------------
__device__ __align__(16) float  g_lat[Kk * Zz];
__device__ __align__(16) __half g_wA [Nn * KP];            // 4.2 MB
__device__ __align__(16) __half g_spT[(size_t)Ntot * KP];  // 16.8 MB

// ---------------------------------------------------------------------------
// PTX helpers (sm_80-era; valid on plain compute_103 target)
// ---------------------------------------------------------------------------
__device__ __forceinline__ uint32_t smem_u32(const void* p) {
    uint32_t a;
    asm("{ .reg .u64 t; cvta.to.shared.u64 t, %1; cvt.u32.u64 %0, t; }"
        : "=r"(a) : "l"(p));
    return a;
}
#define CP_ASYNC16(dst, src) \
    asm volatile("cp.async.cg.shared.global [%0], [%1], 16;" :: "r"(dst), "l"(src))
#define CP_COMMIT() asm volatile("cp.async.commit_group;" ::: "memory")
#define CP_WAIT1()  asm volatile("cp.async.wait_group 1;" ::: "memory")

#define LDSM4(r0, r1, r2, r3, addr) \
    asm volatile("ldmatrix.sync.aligned.m8n8.x4.shared.b16 {%0,%1,%2,%3}, [%4];" \
        : "=r"(r0), "=r"(r1), "=r"(r2), "=r"(r3) : "r"(addr))

__device__ __forceinline__ void mma16816(float* c, const uint32_t* a,
                                         const uint32_t* b) {
    asm volatile(
        "mma.sync.aligned.m16n8k16.row.col.f32.f16.f16.f32 "
        "{%0,%1,%2,%3}, {%4,%5,%6,%7}, {%8,%9}, {%0,%1,%2,%3};"
        : "+f"(c[0]), "+f"(c[1]), "+f"(c[2]), "+f"(c[3])
        : "r"(a[0]), "r"(a[1]), "r"(a[2]), "r"(a[3]), "r"(b[0]), "r"(b[1]));
}

// ---------------------------------------------------------------------------
// R-row block reductions over 128 threads
// ---------------------------------------------------------------------------
template <int R>
__device__ __forceinline__ void redsumN(float v[R], float red[4][R], int t) {
    #pragma unroll
    for (int o = 16; o; o >>= 1)
        #pragma unroll
        for (int r = 0; r < R; r++) v[r] += __shfl_down_sync(0xffffffffu, v[r], o);
    if ((t & 31) == 0)
        #pragma unroll
        for (int r = 0; r < R; r++) red[t >> 5][r] = v[r];
    __syncthreads();
    #pragma unroll
    for (int r = 0; r < R; r++)
        v[r] = red[0][r] + red[1][r] + red[2][r] + red[3][r];
    __syncthreads();
}
template <int R>
__device__ __forceinline__ void redmaxN(float v[R], float red[4][R], int t) {
    #pragma unroll
    for (int o = 16; o; o >>= 1)
        #pragma unroll
        for (int r = 0; r < R; r++)
            v[r] = fmaxf(v[r], __shfl_down_sync(0xffffffffu, v[r], o));
    if ((t & 31) == 0)
        #pragma unroll
        for (int r = 0; r < R; r++) red[t >> 5][r] = v[r];
    __syncthreads();
    #pragma unroll
    for (int r = 0; r < R; r++)
        v[r] = fmaxf(fmaxf(red[0][r], red[1][r]), fmaxf(red[2][r], red[3][r]));
    __syncthreads();
}

// ---------------------------------------------------------------------------
// Kernel 1: lat = LN(latents @ linear_w^T + linear_b), 4 latents per block
// ---------------------------------------------------------------------------
__global__ void k_lat(const float* __restrict__ latents,
                      const float* __restrict__ lw,
                      const float* __restrict__ lb) {
    int k0 = blockIdx.x * 4;
    int t = threadIdx.x;
    __shared__ float lv[4][DS];
    __shared__ float red[4][4];

    #pragma unroll
    for (int r = 0; r < 4; r++) {
        int k = k0 + r;
        float a = 0.f, b2 = 0.f;
        if (k < Kk) { a = latents[k * DS + t]; b2 = latents[k * DS + t + 128]; }
        lv[r][t] = a; lv[r][t + 128] = b2;
    }
    __syncthreads();

    const float* wrow = lw + t * DS;
    float s[4] = {lb[t], lb[t], lb[t], lb[t]};
    #pragma unroll 4
    for (int d = 0; d < DS; d++) {
        float w = wrow[d];
        #pragma unroll
        for (int r = 0; r < 4; r++) s[r] += lv[r][d] * w;
    }

    float v[4];
    #pragma unroll
    for (int r = 0; r < 4; r++) v[r] = s[r];
    redsumN<4>(v, red, t);
    float d4[4];
    #pragma unroll
    for (int r = 0; r < 4; r++) {
        d4[r] = s[r] - v[r] * (1.f / 128.f);
        v[r] = d4[r] * d4[r];
    }
    redsumN<4>(v, red, t);
    #pragma unroll
    for (int r = 0; r < 4; r++) {
        int k = k0 + r;
        if (k < Kk)
            g_lat[k * Zz + t] = d4[r] * rsqrtf(v[r] * (1.f / 128.f) + EPSV);
    }
}

// ---------------------------------------------------------------------------
// Shared-memory overlays for fused k_row | k_prep
// ---------------------------------------------------------------------------
struct RowSh  {
    float xv[8][Cc];
    float av[8][Zz];
    float lg[8][KL];
    float red[4][8];
};
struct PrepSh { float tile[64][65]; };

// ---------------------------------------------------------------------------
// Fused launch 2: blocks [0,512) -> k_row (needs g_lat) ;
//                 blocks [512, 512+2048) -> k_prep (independent)
// 128 threads per block.
// ---------------------------------------------------------------------------
__global__ void k_row_prep(const float* __restrict__ x,
                           const float* __restrict__ blankl,
                           const float* __restrict__ aw,
                           const float* __restrict__ ab,
                           const float* __restrict__ proto,
                           const float* __restrict__ masks,
                           float* __restrict__ out) {
    __shared__ __align__(16) char shbuf[sizeof(RowSh) > sizeof(PrepSh)
                                        ? sizeof(RowSh) : sizeof(PrepSh)];
    int t = threadIdx.x;

    if (blockIdx.x >= 512) {
        // ---- k_prep: sprite^T fp16, 64x64 tile transpose ----
        PrepSh& sh = *(PrepSh*)shbuf;
        int bi = blockIdx.x - 512;         // 0..2047
        int n0 = (bi & 255) * 64;          // Ntot/64 = 256
        int k0 = (bi >> 8) * 64;           // KP/64 = 8

        for (int idx = t; idx < 4096; idx += 128) {
            int kk = idx >> 6, nn = idx & 63;
            int k = k0 + kk, n = n0 + nn;
            int ch = n >> 12, i = n & 4095;
            float s = 0.f;
            if (k < Kk)
                s = (ch < 3) ? proto[(size_t)k * (3 * HW) + ch * HW + i]
                             : masks[(size_t)k * HW + i];
            sh.tile[kk][nn] = s;
        }
        __syncthreads();

        for (int idx = t; idx < 4096; idx += 128) {
            int nn = idx >> 6, kk = idx & 63;
            if (k0 + kk < Kk)
                g_spT[(size_t)(n0 + nn) * KP + k0 + kk] =
                    __float2half(sh.tile[kk][nn]);
        }
        return;
    }

    // ---- k_row: 8 rows per block (same p, 8 consecutive b) ----
    RowSh& sh = *(RowSh*)shbuf;
    int bi = blockIdx.x;          // 0..511
    int p  = bi & 127;
    int bq = bi >> 7;             // 0..3 -> b = bq*8 + r

    #pragma unroll
    for (int r = 0; r < 8; r++)
        sh.xv[r][t] = x[(size_t)(bq * 8 + r) * (Cc * Pp) + t * Pp + p];
    __syncthreads();

    // anchors linear + LN (8 rows)
    {
        const float* wrow = aw + t * Cc;
        float s[8];
        #pragma unroll
        for (int r = 0; r < 8; r++) s[r] = ab[t];
        #pragma unroll 4
        for (int c = 0; c < Cc; c++) {
            float w = wrow[c];
            #pragma unroll
            for (int r = 0; r < 8; r++) s[r] += sh.xv[r][c] * w;
        }
        float v[8];
        #pragma unroll
        for (int r = 0; r < 8; r++) v[r] = s[r];
        redsumN<8>(v, sh.red, t);
        float d8[8];
        #pragma unroll
        for (int r = 0; r < 8; r++) {
            d8[r] = s[r] - v[r] * (1.f / 128.f);
            v[r] = d8[r] * d8[r];
        }
        redsumN<8>(v, sh.red, t);
        #pragma unroll
        for (int r = 0; r < 8; r++)
            sh.av[r][t] = d8[r] * rsqrtf(v[r] * (1.f / 128.f) + EPSV);
    }

    // blank dots (8 rows)
    float lgb[8];
    {
        float bl = blankl[(p & 1) * Cc + t];
        float v[8];
        #pragma unroll
        for (int r = 0; r < 8; r++) v[r] = sh.xv[r][t] * bl;
        redsumN<8>(v, sh.red, t);
        #pragma unroll
        for (int r = 0; r < 8; r++) lgb[r] = v[r] * INV_NORM;
    }
    __syncthreads();   // av visible

    // logits: thread handles k = t + 128*j for all 8 rows
    #pragma unroll
    for (int j = 0; j < 4; j++) {
        int k = t + (j << 7);
        if (k < Kk) {
            const float4* lr = (const float4*)(g_lat + k * Zz);
            float acc[8] = {0.f, 0.f, 0.f, 0.f, 0.f, 0.f, 0.f, 0.f};
            #pragma unroll 4
            for (int i = 0; i < 32; i++) {
                float4 q = lr[i];
                #pragma unroll
                for (int r = 0; r < 8; r++)
                    acc[r] += q.x * sh.av[r][4 * i]     + q.y * sh.av[r][4 * i + 1]
                            + q.z * sh.av[r][4 * i + 2] + q.w * sh.av[r][4 * i + 3];
            }
            #pragma unroll
            for (int r = 0; r < 8; r++) sh.lg[r][k] = acc[r] * INV_NORM;
        } else {
            #pragma unroll
            for (int r = 0; r < 8; r++) sh.lg[r][k] = lgb[r];
        }
    }
    __syncthreads();

    // softmax over 512, 8 rows
    float v[8];
    #pragma unroll
    for (int r = 0; r < 8; r++) {
        float m = -1e30f;
        #pragma unroll
        for (int j = 0; j < 4; j++) m = fmaxf(m, sh.lg[r][t + (j << 7)]);
        v[r] = m;
    }
    redmaxN<8>(v, sh.red, t);
    float mx[8];
    #pragma unroll
    for (int r = 0; r < 8; r++) mx[r] = v[r];

    float ev[8][4];
    #pragma unroll
    for (int r = 0; r < 8; r++) {
        float s = 0.f;
        #pragma unroll
        for (int j = 0; j < 4; j++) {
            ev[r][j] = expf(sh.lg[r][t + (j << 7)] - mx[r]);
            s += ev[r][j];
        }
        v[r] = s;
    }
    redsumN<8>(v, sh.red, t);

    #pragma unroll
    for (int r = 0; r < 8; r++) {
        int b = bq * 8 + r;
        int n = (b << 7) + p;
        int m = (p << 5) + b;
        float inv_sum = 1.0f / v[r];
        float lse = mx[r] + logf(v[r]);
        float* out_w  = out + OFF_W  + (size_t)n * KL;
        float* out_l  = out + OFF_L  + (size_t)n * KL;
        float* out_lp = out + OFF_LP + (size_t)m * KL;
        __half* wa = g_wA + (size_t)m * KP;
        #pragma unroll
        for (int j = 0; j < 4; j++) {
            int k = t + (j << 7);
            float l = sh.lg[r][k];
            float w = ev[r][j] * inv_sum;
            out_w[k]  = w;
            out_l[k]  = l;
            out_lp[k] = l - lse;
            wa[k] = __float2half(w);
        }
    }
}

// ---------------------------------------------------------------------------
// Kernel 4: mma.sync fp16 GEMM  C[4096,16384] = A[4096,512] @ B[16384,512]^T
// CTA 128x128x32, 8 warps, 3-stage cp.async pipeline, 2 CTAs/SM  (round-10)
// ---------------------------------------------------------------------------
__global__ void __launch_bounds__(256, 2) k_gemm(float* __restrict__ outS) {
    extern __shared__ __align__(128) char sm[];   // STAGES x [A|B]

    int t = threadIdx.x;
    int lane = t & 31;
    int wid = t >> 5;
    int warp_m = wid & 3;          // 32-row slice
    int warp_n = wid >> 2;         // 64-col slice
    int n0 = blockIdx.x * TN;
    int m0 = blockIdx.y * TM;

    uint32_t smb = smem_u32(sm);

    // cp.async mapping: thread covers rows qr0 and qr0+64, 16B chunk qc
    int qr0 = t >> 2, qc = t & 3;
    int qr1 = qr0 + 64;

    const char* gA0 = (const char*)g_wA  + (size_t)(m0 + qr0) * (KP * 2) + qc * 16;
    const char* gA1 = (const char*)g_wA  + (size_t)(m0 + qr1) * (KP * 2) + qc * 16;
    const char* gB0 = (const char*)g_spT + (size_t)(n0 + qr0) * (KP * 2) + qc * 16;
    const char* gB1 = (const char*)g_spT + (size_t)(n0 + qr1) * (KP * 2) + qc * 16;

    uint32_t sA0 = smb + qr0 * RP + qc * 16;
    uint32_t sA1 = smb + qr1 * RP + qc * 16;
    uint32_t sB0 = sA0 + TILE_BYTES;
    uint32_t sB1 = sA1 + TILE_BYTES;

    uint32_t lmA = smb + (warp_m * 32 + (lane & 15)) * RP + (lane >> 4) * 16;
    uint32_t lmB = smb + TILE_BYTES
                 + (warp_n * 64 + (lane & 7) + ((lane >> 4) & 1) * 8) * RP
                 + ((lane >> 3) & 1) * 16;

    float acc[2][8][4];
    #pragma unroll
    for (int mt = 0; mt < 2; mt++)
        #pragma unroll
        for (int nt = 0; nt < 8; nt++)
            #pragma unroll
            for (int q = 0; q < 4; q++) acc[mt][nt][q] = 0.f;

    // prefetch chunks 0,1 into stages 0,1
    #pragma unroll
    for (int s = 0; s < STAGES - 1; s++) {
        uint32_t so = s * STAGE_BYTES;
        int cb = s * 64;
        CP_ASYNC16(sA0 + so, gA0 + cb);
        CP_ASYNC16(sA1 + so, gA1 + cb);
        CP_ASYNC16(sB0 + so, gB0 + cb);
        CP_ASYNC16(sB1 + so, gB1 + cb);
        CP_COMMIT();
    }

    for (int c = 0; c < NCHUNK; c++) {
        CP_WAIT1();            // chunk c landed
        __syncthreads();       // all warps past compute of c-1 -> stage reuse safe

        // issue chunk c+2 into stage (c+2)%STAGES; always commit (group count)
        int cn = c + STAGES - 1;
        if (cn < NCHUNK) {
            uint32_t so = (cn % STAGES) * STAGE_BYTES;
            int cb = cn * 64;
            CP_ASYNC16(sA0 + so, gA0 + cb);
            CP_ASYNC16(sA1 + so, gA1 + cb);
            CP_ASYNC16(sB0 + so, gB0 + cb);
            CP_ASYNC16(sB1 + so, gB1 + cb);
        }
        CP_COMMIT();

        uint32_t aoff = lmA + (c % STAGES) * STAGE_BYTES;
        uint32_t boff = lmB + (c % STAGES) * STAGE_BYTES;
        #pragma unroll
        for (int kt = 0; kt < 2; kt++) {
            uint32_t a[2][4];
            #pragma unroll
            for (int mt = 0; mt < 2; mt++)
                LDSM4(a[mt][0], a[mt][1], a[mt][2], a[mt][3],
                      aoff + mt * (16 * RP) + kt * 32);
            uint32_t bfr[8][2];
            #pragma unroll
            for (int pg = 0; pg < 4; pg++)
                LDSM4(bfr[2 * pg][0], bfr[2 * pg][1],
                      bfr[2 * pg + 1][0], bfr[2 * pg + 1][1],
                      boff + pg * (16 * RP) + kt * 32);
            #pragma unroll
            for (int mt = 0; mt < 2; mt++)
                #pragma unroll
                for (int nt = 0; nt < 8; nt++)
                    mma16816(acc[mt][nt], a[mt], bfr[nt]);
        }
    }

    // epilogue
    int rbase = m0 + warp_m * 32 + (lane >> 2);
    int cbase = n0 + warp_n * 64 + (lane & 3) * 2;
    #pragma unroll
    for (int mt = 0; mt < 2; mt++) {
        #pragma unroll
        for (int nt = 0; nt < 8; nt++) {
            int r = rbase + mt * 16;
            int cc = cbase + nt * 8;
            *(float2*)(outS + (size_t)r * Ntot + cc) =
                make_float2(acc[mt][nt][0], acc[mt][nt][1]);
            *(float2*)(outS + (size_t)(r + 8) * Ntot + cc) =
                make_float2(acc[mt][nt][2], acc[mt][nt][3]);
        }
    }
}

// ---------------------------------------------------------------------------
// Launch
// ---------------------------------------------------------------------------
extern "C" void kernel_launch(void* const* d_in, const int* in_sizes, int n_in,
                              void* d_out, int out_size) {
    const float* x       = (const float*)d_in[0];
    const float* latents = (const float*)d_in[1];
    const float* blankl  = (const float*)d_in[2];
    const float* lw      = (const float*)d_in[3];
    const float* lb      = (const float*)d_in[4];
    const float* aw      = (const float*)d_in[5];
    const float* ab      = (const float*)d_in[6];
    const float* proto   = (const float*)d_in[7];
    const float* masks   = (const float*)d_in[8];
    float* out = (float*)d_out;

    static int smem_set = 0;
    if (!smem_set) {
        cudaFuncSetAttribute(k_gemm, cudaFuncAttributeMaxDynamicSharedMemorySize,
                             SMEM_DYN);
        smem_set = 1;
    }

    // launch 1: codebook latents LN (small)
    k_lat<<<128, 128>>>(latents, lw, lb);
    // launch 2: k_row (blocks 0..511, needs g_lat) || k_prep (blocks 512..2559)
    k_row_prep<<<512 + 2048, 128>>>(x, blankl, aw, ab, proto, masks, out);
    // launch 3: tensor-core GEMM (needs g_wA, g_spT)
    dim3 gg(Ntot / TN, Nn / TM);
    k_gemm<<<gg, 256, SMEM_DYN>>>(out + OFF_S);
}

// round 14
// speedup vs baseline: 1.2284x; 1.0282x over previous
#include <cuda_runtime.h>
#include <cuda_fp16.h>
#include <math.h>
#include <stdint.h>

// ---------------------------------------------------------------------------
// Problem constants
// ---------------------------------------------------------------------------
#define Bb   32
#define Cc   128
#define Pp   128
#define Nn   (Bb * Pp)    // 4096 rows
#define Kk   510
#define KL   512
#define Zz   128
#define DS   256
#define HW   4096
#define EPSV 1e-5f
#define INV_NORM 0.08838834764831845f

#define KP   512
#define Ntot 16384        // 4*HW

// output layout
#define OFF_W   0
#define OFF_L   (Nn * KL)
#define OFF_LP  (2 * Nn * KL)
#define OFF_S   (3 * Nn * KL)

// GEMM tiling: CTA 128x128x32, 3-stage cp.async pipeline (round-10 proven)
#define TM 128
#define TN 128
#define TK 32                 // fp16 per k-chunk (64 B per row)
#define NCHUNK (KP / TK)      // 16
#define RP 80                 // smem row pitch (64B data + 16B pad)
#define TILE_BYTES (128 * RP) // 10240
#define STAGE_BYTES (2 * TILE_BYTES)
#define STAGES 3
#define SMEM_DYN (STAGES * STAGE_BYTES)   // 61440

// fused launch-1 block ranges
#define NB_LAT  128
#define NB_ROW  512
#define NB_PREP 2048

// ---------------------------------------------------------------------------
// Device scratch (zero-initialized; rows k>=510 of g_spT stay zero)
// ---------------------------------------------------------------------------
__device__ __align__(16) float  g_lat[Kk * Zz];
__device__ __align__(16) __half g_wA [Nn * KP];            // 4.2 MB
__device__ __align__(16) __half g_spT[(size_t)Ntot * KP];  // 16.8 MB
__device__ int g_sync = 0;                                  // lat-done counter

// ---------------------------------------------------------------------------
// PTX helpers (sm_80-era; valid on plain compute_103 target)
// ---------------------------------------------------------------------------
__device__ __forceinline__ uint32_t smem_u32(const void* p) {
    uint32_t a;
    asm("{ .reg .u64 t; cvta.to.shared.u64 t, %1; cvt.u32.u64 %0, t; }"
        : "=r"(a) : "l"(p));
    return a;
}
#define CP_ASYNC16(dst, src) \
    asm volatile("cp.async.cg.shared.global [%0], [%1], 16;" :: "r"(dst), "l"(src))
#define CP_COMMIT() asm volatile("cp.async.commit_group;" ::: "memory")
#define CP_WAIT1()  asm volatile("cp.async.wait_group 1;" ::: "memory")

#define LDSM4(r0, r1, r2, r3, addr) \
    asm volatile("ldmatrix.sync.aligned.m8n8.x4.shared.b16 {%0,%1,%2,%3}, [%4];" \
        : "=r"(r0), "=r"(r1), "=r"(r2), "=r"(r3) : "r"(addr))

__device__ __forceinline__ void mma16816(float* c, const uint32_t* a,
                                         const uint32_t* b) {
    asm volatile(
        "mma.sync.aligned.m16n8k16.row.col.f32.f16.f16.f32 "
        "{%0,%1,%2,%3}, {%4,%5,%6,%7}, {%8,%9}, {%0,%1,%2,%3};"
        : "+f"(c[0]), "+f"(c[1]), "+f"(c[2]), "+f"(c[3])
        : "r"(a[0]), "r"(a[1]), "r"(a[2]), "r"(a[3]), "r"(b[0]), "r"(b[1]));
}

// ---------------------------------------------------------------------------
// R-row block reductions over 128 threads
// ---------------------------------------------------------------------------
template <int R>
__device__ __forceinline__ void redsumN(float v[R], float red[4][R], int t) {
    #pragma unroll
    for (int o = 16; o; o >>= 1)
        #pragma unroll
        for (int r = 0; r < R; r++) v[r] += __shfl_down_sync(0xffffffffu, v[r], o);
    if ((t & 31) == 0)
        #pragma unroll
        for (int r = 0; r < R; r++) red[t >> 5][r] = v[r];
    __syncthreads();
    #pragma unroll
    for (int r = 0; r < R; r++)
        v[r] = red[0][r] + red[1][r] + red[2][r] + red[3][r];
    __syncthreads();
}
template <int R>
__device__ __forceinline__ void redmaxN(float v[R], float red[4][R], int t) {
    #pragma unroll
    for (int o = 16; o; o >>= 1)
        #pragma unroll
        for (int r = 0; r < R; r++)
            v[r] = fmaxf(v[r], __shfl_down_sync(0xffffffffu, v[r], o));
    if ((t & 31) == 0)
        #pragma unroll
        for (int r = 0; r < R; r++) red[t >> 5][r] = v[r];
    __syncthreads();
    #pragma unroll
    for (int r = 0; r < R; r++)
        v[r] = fmaxf(fmaxf(red[0][r], red[1][r]), fmaxf(red[2][r], red[3][r]));
    __syncthreads();
}

// ---------------------------------------------------------------------------
// Shared-memory overlays for the fused kernel (lat | row | prep)
// ---------------------------------------------------------------------------
struct LatSh {
    float lv[4][DS];       // 4 KB
    float lws[128][33];    // 16.9 KB staged lw tile (32 d-cols, pad to 33)
    float red[4][4];
};
struct RowSh {
    float xv[8][Cc];
    float av[8][Zz];
    float lg[8][KL];
    float red[4][8];
};
struct PrepSh { float tile[64][65]; };

#define MAXSH(a, b) ((a) > (b) ? (a) : (b))
#define SHBYTES MAXSH(sizeof(LatSh), MAXSH(sizeof(RowSh), sizeof(PrepSh)))

// ---------------------------------------------------------------------------
// Fused launch 1:
//   bids [0, 128)        -> k_lat (4 latents each; signals g_sync)
//   bids [128, 640)      -> k_row (spins on g_sync == NB_LAT)
//   bids [640, 2688)     -> k_prep (independent)
// ---------------------------------------------------------------------------
__global__ void __launch_bounds__(128) k_fused(
        const float* __restrict__ latents,
        const float* __restrict__ lw,
        const float* __restrict__ lb,
        const float* __restrict__ x,
        const float* __restrict__ blankl,
        const float* __restrict__ aw,
        const float* __restrict__ ab,
        const float* __restrict__ proto,
        const float* __restrict__ masks,
        float* __restrict__ out) {
    __shared__ __align__(16) char shbuf[SHBYTES];
    int t = threadIdx.x;
    int bid = blockIdx.x;

    if (bid < NB_LAT) {
        // ================= k_lat: 4 latents per block ======================
        LatSh& sh = *(LatSh*)shbuf;
        int k0 = bid * 4;

        #pragma unroll
        for (int r = 0; r < 4; r++) {
            int k = k0 + r;
            float a = 0.f, b2 = 0.f;
            if (k < Kk) { a = latents[k * DS + t]; b2 = latents[k * DS + t + 128]; }
            sh.lv[r][t] = a; sh.lv[r][t + 128] = b2;
        }
        __syncthreads();

        float s[4] = {lb[t], lb[t], lb[t], lb[t]};
        // 8 tiles of 32 d-columns, lw staged through smem (coalesced loads)
        for (int dt = 0; dt < 8; dt++) {
            int d0 = dt * 32;
            #pragma unroll
            for (int i = 0; i < 32; i++) {
                int idx = i * 128 + t;          // 0..4095
                int z = idx >> 5, dd = idx & 31;
                sh.lws[z][dd] = lw[z * DS + d0 + dd];
            }
            __syncthreads();
            #pragma unroll 8
            for (int dd = 0; dd < 32; dd++) {
                float w = sh.lws[t][dd];
                #pragma unroll
                for (int r = 0; r < 4; r++) s[r] += sh.lv[r][d0 + dd] * w;
            }
            __syncthreads();
        }

        float v[4];
        #pragma unroll
        for (int r = 0; r < 4; r++) v[r] = s[r];
        redsumN<4>(v, sh.red, t);
        float d4[4];
        #pragma unroll
        for (int r = 0; r < 4; r++) {
            d4[r] = s[r] - v[r] * (1.f / 128.f);
            v[r] = d4[r] * d4[r];
        }
        redsumN<4>(v, sh.red, t);
        #pragma unroll
        for (int r = 0; r < 4; r++) {
            int k = k0 + r;
            if (k < Kk)
                g_lat[k * Zz + t] = d4[r] * rsqrtf(v[r] * (1.f / 128.f) + EPSV);
        }
        __threadfence();
        __syncthreads();
        if (t == 0) atomicAdd(&g_sync, 1);
        return;
    }

    if (bid >= NB_LAT + NB_ROW) {
        // ================= k_prep: sprite^T fp16 ===========================
        PrepSh& sh = *(PrepSh*)shbuf;
        int bi = bid - (NB_LAT + NB_ROW);  // 0..2047
        int n0 = (bi & 255) * 64;          // Ntot/64 = 256
        int k0 = (bi >> 8) * 64;           // KP/64 = 8

        for (int idx = t; idx < 4096; idx += 128) {
            int kk = idx >> 6, nn = idx & 63;
            int k = k0 + kk, n = n0 + nn;
            int ch = n >> 12, i = n & 4095;
            float s = 0.f;
            if (k < Kk)
                s = (ch < 3) ? proto[(size_t)k * (3 * HW) + ch * HW + i]
                             : masks[(size_t)k * HW + i];
            sh.tile[kk][nn] = s;
        }
        __syncthreads();

        for (int idx = t; idx < 4096; idx += 128) {
            int nn = idx >> 6, kk = idx & 63;
            if (k0 + kk < Kk)
                g_spT[(size_t)(n0 + nn) * KP + k0 + kk] =
                    __float2half(sh.tile[kk][nn]);
        }
        return;
    }

    // ================= k_row: 8 rows per block =============================
    RowSh& sh = *(RowSh*)shbuf;
    int bi = bid - NB_LAT;        // 0..511
    int p  = bi & 127;
    int bq = bi >> 7;             // 0..3 -> b = bq*8 + r

    // load xv while waiting is fine (doesn't depend on g_lat)
    #pragma unroll
    for (int r = 0; r < 8; r++)
        sh.xv[r][t] = x[(size_t)(bq * 8 + r) * (Cc * Pp) + t * Pp + p];

    // wait for all lat blocks (dispatched first — lowest bids — so no deadlock)
    if (t == 0) {
        while (atomicAdd(&g_sync, 0) < NB_LAT) __nanosleep(128);
    }
    __syncthreads();
    __threadfence();   // acquire: g_lat writes visible

    // anchors linear + LN (8 rows)
    {
        const float* wrow = aw + t * Cc;
        float s[8];
        #pragma unroll
        for (int r = 0; r < 8; r++) s[r] = ab[t];
        #pragma unroll 4
        for (int c = 0; c < Cc; c++) {
            float w = wrow[c];
            #pragma unroll
            for (int r = 0; r < 8; r++) s[r] += sh.xv[r][c] * w;
        }
        float v[8];
        #pragma unroll
        for (int r = 0; r < 8; r++) v[r] = s[r];
        redsumN<8>(v, sh.red, t);
        float d8[8];
        #pragma unroll
        for (int r = 0; r < 8; r++) {
            d8[r] = s[r] - v[r] * (1.f / 128.f);
            v[r] = d8[r] * d8[r];
        }
        redsumN<8>(v, sh.red, t);
        #pragma unroll
        for (int r = 0; r < 8; r++)
            sh.av[r][t] = d8[r] * rsqrtf(v[r] * (1.f / 128.f) + EPSV);
    }

    // blank dots (8 rows)
    float lgb[8];
    {
        float bl = blankl[(p & 1) * Cc + t];
        float v[8];
        #pragma unroll
        for (int r = 0; r < 8; r++) v[r] = sh.xv[r][t] * bl;
        redsumN<8>(v, sh.red, t);
        #pragma unroll
        for (int r = 0; r < 8; r++) lgb[r] = v[r] * INV_NORM;
    }
    __syncthreads();   // av visible

    // logits: thread handles k = t + 128*j for all 8 rows
    #pragma unroll
    for (int j = 0; j < 4; j++) {
        int k = t + (j << 7);
        if (k < Kk) {
            const float4* lr = (const float4*)(g_lat + k * Zz);
            float acc[8] = {0.f, 0.f, 0.f, 0.f, 0.f, 0.f, 0.f, 0.f};
            #pragma unroll 4
            for (int i = 0; i < 32; i++) {
                float4 q = lr[i];
                #pragma unroll
                for (int r = 0; r < 8; r++)
                    acc[r] += q.x * sh.av[r][4 * i]     + q.y * sh.av[r][4 * i + 1]
                            + q.z * sh.av[r][4 * i + 2] + q.w * sh.av[r][4 * i + 3];
            }
            #pragma unroll
            for (int r = 0; r < 8; r++) sh.lg[r][k] = acc[r] * INV_NORM;
        } else {
            #pragma unroll
            for (int r = 0; r < 8; r++) sh.lg[r][k] = lgb[r];
        }
    }
    __syncthreads();

    // softmax over 512, 8 rows
    float v[8];
    #pragma unroll
    for (int r = 0; r < 8; r++) {
        float m = -1e30f;
        #pragma unroll
        for (int j = 0; j < 4; j++) m = fmaxf(m, sh.lg[r][t + (j << 7)]);
        v[r] = m;
    }
    redmaxN<8>(v, sh.red, t);
    float mx[8];
    #pragma unroll
    for (int r = 0; r < 8; r++) mx[r] = v[r];

    float ev[8][4];
    #pragma unroll
    for (int r = 0; r < 8; r++) {
        float s = 0.f;
        #pragma unroll
        for (int j = 0; j < 4; j++) {
            ev[r][j] = expf(sh.lg[r][t + (j << 7)] - mx[r]);
            s += ev[r][j];
        }
        v[r] = s;
    }
    redsumN<8>(v, sh.red, t);

    #pragma unroll
    for (int r = 0; r < 8; r++) {
        int b = bq * 8 + r;
        int n = (b << 7) + p;
        int m = (p << 5) + b;
        float inv_sum = 1.0f / v[r];
        float lse = mx[r] + logf(v[r]);
        float* out_w  = out + OFF_W  + (size_t)n * KL;
        float* out_l  = out + OFF_L  + (size_t)n * KL;
        float* out_lp = out + OFF_LP + (size_t)m * KL;
        __half* wa = g_wA + (size_t)m * KP;
        #pragma unroll
        for (int j = 0; j < 4; j++) {
            int k = t + (j << 7);
            float l = sh.lg[r][k];
            float w = ev[r][j] * inv_sum;
            out_w[k]  = w;
            out_l[k]  = l;
            out_lp[k] = l - lse;
            wa[k] = __float2half(w);
        }
    }
}

// ---------------------------------------------------------------------------
// Kernel 4: mma.sync fp16 GEMM  C[4096,16384] = A[4096,512] @ B[16384,512]^T
// CTA 128x128x32, 8 warps, 3-stage cp.async pipeline, 2 CTAs/SM  (round-10)
// ---------------------------------------------------------------------------
__global__ void __launch_bounds__(256, 2) k_gemm(float* __restrict__ outS) {
    extern __shared__ __align__(128) char sm[];   // STAGES x [A|B]

    // reset the fused-kernel sync counter for the next graph replay
    if (blockIdx.x == 0 && blockIdx.y == 0 && threadIdx.x == 0) g_sync = 0;

    int t = threadIdx.x;
    int lane = t & 31;
    int wid = t >> 5;
    int warp_m = wid & 3;          // 32-row slice
    int warp_n = wid >> 2;         // 64-col slice
    int n0 = blockIdx.x * TN;
    int m0 = blockIdx.y * TM;

    uint32_t smb = smem_u32(sm);

    // cp.async mapping: thread covers rows qr0 and qr0+64, 16B chunk qc
    int qr0 = t >> 2, qc = t & 3;
    int qr1 = qr0 + 64;

    const char* gA0 = (const char*)g_wA  + (size_t)(m0 + qr0) * (KP * 2) + qc * 16;
    const char* gA1 = (const char*)g_wA  + (size_t)(m0 + qr1) * (KP * 2) + qc * 16;
    const char* gB0 = (const char*)g_spT + (size_t)(n0 + qr0) * (KP * 2) + qc * 16;
    const char* gB1 = (const char*)g_spT + (size_t)(n0 + qr1) * (KP * 2) + qc * 16;

    uint32_t sA0 = smb + qr0 * RP + qc * 16;
    uint32_t sA1 = smb + qr1 * RP + qc * 16;
    uint32_t sB0 = sA0 + TILE_BYTES;
    uint32_t sB1 = sA1 + TILE_BYTES;

    uint32_t lmA = smb + (warp_m * 32 + (lane & 15)) * RP + (lane >> 4) * 16;
    uint32_t lmB = smb + TILE_BYTES
                 + (warp_n * 64 + (lane & 7) + ((lane >> 4) & 1) * 8) * RP
                 + ((lane >> 3) & 1) * 16;

    float acc[2][8][4];
    #pragma unroll
    for (int mt = 0; mt < 2; mt++)
        #pragma unroll
        for (int nt = 0; nt < 8; nt++)
            #pragma unroll
            for (int q = 0; q < 4; q++) acc[mt][nt][q] = 0.f;

    // prefetch chunks 0,1 into stages 0,1
    #pragma unroll
    for (int s = 0; s < STAGES - 1; s++) {
        uint32_t so = s * STAGE_BYTES;
        int cb = s * 64;
        CP_ASYNC16(sA0 + so, gA0 + cb);
        CP_ASYNC16(sA1 + so, gA1 + cb);
        CP_ASYNC16(sB0 + so, gB0 + cb);
        CP_ASYNC16(sB1 + so, gB1 + cb);
        CP_COMMIT();
    }

    for (int c = 0; c < NCHUNK; c++) {
        CP_WAIT1();            // chunk c landed
        __syncthreads();       // all warps past compute of c-1 -> stage reuse safe

        // issue chunk c+2 into stage (c+2)%STAGES; always commit (group count)
        int cn = c + STAGES - 1;
        if (cn < NCHUNK) {
            uint32_t so = (cn % STAGES) * STAGE_BYTES;
            int cb = cn * 64;
            CP_ASYNC16(sA0 + so, gA0 + cb);
            CP_ASYNC16(sA1 + so, gA1 + cb);
            CP_ASYNC16(sB0 + so, gB0 + cb);
            CP_ASYNC16(sB1 + so, gB1 + cb);
        }
        CP_COMMIT();

        uint32_t aoff = lmA + (c % STAGES) * STAGE_BYTES;
        uint32_t boff = lmB + (c % STAGES) * STAGE_BYTES;
        #pragma unroll
        for (int kt = 0; kt < 2; kt++) {
            uint32_t a[2][4];
            #pragma unroll
            for (int mt = 0; mt < 2; mt++)
                LDSM4(a[mt][0], a[mt][1], a[mt][2], a[mt][3],
                      aoff + mt * (16 * RP) + kt * 32);
            uint32_t bfr[8][2];
            #pragma unroll
            for (int pg = 0; pg < 4; pg++)
                LDSM4(bfr[2 * pg][0], bfr[2 * pg][1],
                      bfr[2 * pg + 1][0], bfr[2 * pg + 1][1],
                      boff + pg * (16 * RP) + kt * 32);
            #pragma unroll
            for (int mt = 0; mt < 2; mt++)
                #pragma unroll
                for (int nt = 0; nt < 8; nt++)
                    mma16816(acc[mt][nt], a[mt], bfr[nt]);
        }
    }

    // epilogue
    int rbase = m0 + warp_m * 32 + (lane >> 2);
    int cbase = n0 + warp_n * 64 + (lane & 3) * 2;
    #pragma unroll
    for (int mt = 0; mt < 2; mt++) {
        #pragma unroll
        for (int nt = 0; nt < 8; nt++) {
            int r = rbase + mt * 16;
            int cc = cbase + nt * 8;
            *(float2*)(outS + (size_t)r * Ntot + cc) =
                make_float2(acc[mt][nt][0], acc[mt][nt][1]);
            *(float2*)(outS + (size_t)(r + 8) * Ntot + cc) =
                make_float2(acc[mt][nt][2], acc[mt][nt][3]);
        }
    }
}

// ---------------------------------------------------------------------------
// Launch
// ---------------------------------------------------------------------------
extern "C" void kernel_launch(void* const* d_in, const int* in_sizes, int n_in,
                              void* d_out, int out_size) {
    const float* x       = (const float*)d_in[0];
    const float* latents = (const float*)d_in[1];
    const float* blankl  = (const float*)d_in[2];
    const float* lw      = (const float*)d_in[3];
    const float* lb      = (const float*)d_in[4];
    const float* aw      = (const float*)d_in[5];
    const float* ab      = (const float*)d_in[6];
    const float* proto   = (const float*)d_in[7];
    const float* masks   = (const float*)d_in[8];
    float* out = (float*)d_out;

    static int smem_set = 0;
    if (!smem_set) {
        cudaFuncSetAttribute(k_gemm, cudaFuncAttributeMaxDynamicSharedMemorySize,
                             SMEM_DYN);
        smem_set = 1;
    }

    // launch 1: lat (0..127) + row (128..639, waits on lat) + prep (640..2687)
    k_fused<<<NB_LAT + NB_ROW + NB_PREP, 128>>>(
        latents, lw, lb, x, blankl, aw, ab, proto, masks, out);
    // launch 2: tensor-core GEMM (needs g_wA, g_spT); also resets g_sync
    dim3 gg(Ntot / TN, Nn / TM);
    k_gemm<<<gg, 256, SMEM_DYN>>>(out + OFF_S);
}

// round 15
// speedup vs baseline: 1.2538x; 1.0207x over previous
#include <cuda_runtime.h>
#include <cuda_fp16.h>
#include <math.h>
#include <stdint.h>

// ---------------------------------------------------------------------------
// Problem constants
// ---------------------------------------------------------------------------
#define Bb   32
#define Cc   128
#define Pp   128
#define Nn   (Bb * Pp)    // 4096 rows
#define Kk   510
#define KL   512
#define Zz   128
#define DS   256
#define HW   4096
#define EPSV 1e-5f
#define INV_NORM 0.08838834764831845f

#define KP   512
#define Ntot 16384        // 4*HW

// output layout
#define OFF_W   0
#define OFF_L   (Nn * KL)
#define OFF_LP  (2 * Nn * KL)
#define OFF_S   (3 * Nn * KL)

// GEMM tiling: CTA 128x128x32, 3-stage cp.async pipeline (round-10 proven)
#define TM 128
#define TN 128
#define TK 32                 // fp16 per k-chunk (64 B per row)
#define NCHUNK (KP / TK)      // 16
#define RP 80                 // smem row pitch (64B data + 16B pad)
#define TILE_BYTES (128 * RP) // 10240
#define STAGE_BYTES (2 * TILE_BYTES)
#define STAGES 3
#define SMEM_DYN (STAGES * STAGE_BYTES)   // 61440

// fused launch-1 block ranges
#define NB_LAT  128
#define NB_ROW  512
#define NB_PREP 2048

// ---------------------------------------------------------------------------
// Device scratch (zero-initialized; rows k>=510 of g_spT stay zero)
// ---------------------------------------------------------------------------
__device__ __align__(16) float  g_lat[Kk * Zz];
__device__ __align__(16) __half g_wA [Nn * KP];            // 4.2 MB
__device__ __align__(16) __half g_spT[(size_t)Ntot * KP];  // 16.8 MB
__device__ int g_sync = 0;                                  // lat-done counter

// ---------------------------------------------------------------------------
// PTX helpers (sm_80-era; valid on plain compute_103 target)
// ---------------------------------------------------------------------------
__device__ __forceinline__ uint32_t smem_u32(const void* p) {
    uint32_t a;
    asm("{ .reg .u64 t; cvta.to.shared.u64 t, %1; cvt.u32.u64 %0, t; }"
        : "=r"(a) : "l"(p));
    return a;
}
#define CP_ASYNC16(dst, src) \
    asm volatile("cp.async.cg.shared.global [%0], [%1], 16;" :: "r"(dst), "l"(src))
#define CP_COMMIT() asm volatile("cp.async.commit_group;" ::: "memory")
#define CP_WAIT1()  asm volatile("cp.async.wait_group 1;" ::: "memory")

#define LDSM4(r0, r1, r2, r3, addr) \
    asm volatile("ldmatrix.sync.aligned.m8n8.x4.shared.b16 {%0,%1,%2,%3}, [%4];" \
        : "=r"(r0), "=r"(r1), "=r"(r2), "=r"(r3) : "r"(addr))

__device__ __forceinline__ void mma16816(float* c, const uint32_t* a,
                                         const uint32_t* b) {
    asm volatile(
        "mma.sync.aligned.m16n8k16.row.col.f32.f16.f16.f32 "
        "{%0,%1,%2,%3}, {%4,%5,%6,%7}, {%8,%9}, {%0,%1,%2,%3};"
        : "+f"(c[0]), "+f"(c[1]), "+f"(c[2]), "+f"(c[3])
        : "r"(a[0]), "r"(a[1]), "r"(a[2]), "r"(a[3]), "r"(b[0]), "r"(b[1]));
}

// ---------------------------------------------------------------------------
// R-row block reductions over 128 threads
// ---------------------------------------------------------------------------
template <int R>
__device__ __forceinline__ void redsumN(float v[R], float red[4][R], int t) {
    #pragma unroll
    for (int o = 16; o; o >>= 1)
        #pragma unroll
        for (int r = 0; r < R; r++) v[r] += __shfl_down_sync(0xffffffffu, v[r], o);
    if ((t & 31) == 0)
        #pragma unroll
        for (int r = 0; r < R; r++) red[t >> 5][r] = v[r];
    __syncthreads();
    #pragma unroll
    for (int r = 0; r < R; r++)
        v[r] = red[0][r] + red[1][r] + red[2][r] + red[3][r];
    __syncthreads();
}
template <int R>
__device__ __forceinline__ void redmaxN(float v[R], float red[4][R], int t) {
    #pragma unroll
    for (int o = 16; o; o >>= 1)
        #pragma unroll
        for (int r = 0; r < R; r++)
            v[r] = fmaxf(v[r], __shfl_down_sync(0xffffffffu, v[r], o));
    if ((t & 31) == 0)
        #pragma unroll
        for (int r = 0; r < R; r++) red[t >> 5][r] = v[r];
    __syncthreads();
    #pragma unroll
    for (int r = 0; r < R; r++)
        v[r] = fmaxf(fmaxf(red[0][r], red[1][r]), fmaxf(red[2][r], red[3][r]));
    __syncthreads();
}

// ---------------------------------------------------------------------------
// Shared-memory overlays for the fused kernel (lat | row | prep)
// ---------------------------------------------------------------------------
struct LatSh {
    float lv[4][DS];       // 4 KB
    float lws[128][33];    // 16.9 KB staged lw tile (32 d-cols, pad to 33)
    float red[4][4];
};
struct RowSh {
    float xv[8][Cc];
    float av[8][Zz];
    float lg[8][KL];
    float red[4][8];
};
struct PrepSh { float tile[64][65]; };

#define MAXSH(a, b) ((a) > (b) ? (a) : (b))
#define SHBYTES MAXSH(sizeof(LatSh), MAXSH(sizeof(RowSh), sizeof(PrepSh)))

// ---------------------------------------------------------------------------
// Fused launch 1:
//   bids [0, 128)        -> k_lat (4 latents each; signals g_sync)
//   bids [128, 640)      -> k_row (spins on g_sync == NB_LAT)
//   bids [640, 2688)     -> k_prep (independent)
// ---------------------------------------------------------------------------
__global__ void __launch_bounds__(128) k_fused(
        const float* __restrict__ latents,
        const float* __restrict__ lw,
        const float* __restrict__ lb,
        const float* __restrict__ x,
        const float* __restrict__ blankl,
        const float* __restrict__ aw,
        const float* __restrict__ ab,
        const float* __restrict__ proto,
        const float* __restrict__ masks,
        float* __restrict__ out) {
    __shared__ __align__(16) char shbuf[SHBYTES];
    int t = threadIdx.x;
    int bid = blockIdx.x;

    if (bid < NB_LAT) {
        // ================= k_lat: 4 latents per block ======================
        LatSh& sh = *(LatSh*)shbuf;
        int k0 = bid * 4;

        #pragma unroll
        for (int r = 0; r < 4; r++) {
            int k = k0 + r;
            float a = 0.f, b2 = 0.f;
            if (k < Kk) { a = latents[k * DS + t]; b2 = latents[k * DS + t + 128]; }
            sh.lv[r][t] = a; sh.lv[r][t + 128] = b2;
        }
        __syncthreads();

        float s[4] = {lb[t], lb[t], lb[t], lb[t]};
        // 8 tiles of 32 d-columns, lw staged through smem (coalesced loads)
        for (int dt = 0; dt < 8; dt++) {
            int d0 = dt * 32;
            #pragma unroll
            for (int i = 0; i < 32; i++) {
                int idx = i * 128 + t;          // 0..4095
                int z = idx >> 5, dd = idx & 31;
                sh.lws[z][dd] = lw[z * DS + d0 + dd];
            }
            __syncthreads();
            #pragma unroll 8
            for (int dd = 0; dd < 32; dd++) {
                float w = sh.lws[t][dd];
                #pragma unroll
                for (int r = 0; r < 4; r++) s[r] += sh.lv[r][d0 + dd] * w;
            }
            __syncthreads();
        }

        float v[4];
        #pragma unroll
        for (int r = 0; r < 4; r++) v[r] = s[r];
        redsumN<4>(v, sh.red, t);
        float d4[4];
        #pragma unroll
        for (int r = 0; r < 4; r++) {
            d4[r] = s[r] - v[r] * (1.f / 128.f);
            v[r] = d4[r] * d4[r];
        }
        redsumN<4>(v, sh.red, t);
        #pragma unroll
        for (int r = 0; r < 4; r++) {
            int k = k0 + r;
            if (k < Kk)
                g_lat[k * Zz + t] = d4[r] * rsqrtf(v[r] * (1.f / 128.f) + EPSV);
        }
        __threadfence();
        __syncthreads();
        if (t == 0) atomicAdd(&g_sync, 1);
        return;
    }

    if (bid >= NB_LAT + NB_ROW) {
        // ================= k_prep: sprite^T fp16 ===========================
        PrepSh& sh = *(PrepSh*)shbuf;
        int bi = bid - (NB_LAT + NB_ROW);  // 0..2047
        int n0 = (bi & 255) * 64;          // Ntot/64 = 256
        int k0 = (bi >> 8) * 64;           // KP/64 = 8

        for (int idx = t; idx < 4096; idx += 128) {
            int kk = idx >> 6, nn = idx & 63;
            int k = k0 + kk, n = n0 + nn;
            int ch = n >> 12, i = n & 4095;
            float s = 0.f;
            if (k < Kk)
                s = (ch < 3) ? proto[(size_t)k * (3 * HW) + ch * HW + i]
                             : masks[(size_t)k * HW + i];
            sh.tile[kk][nn] = s;
        }
        __syncthreads();

        for (int idx = t; idx < 4096; idx += 128) {
            int nn = idx >> 6, kk = idx & 63;
            if (k0 + kk < Kk)
                g_spT[(size_t)(n0 + nn) * KP + k0 + kk] =
                    __float2half(sh.tile[kk][nn]);
        }
        return;
    }

    // ================= k_row: 8 rows per block =============================
    RowSh& sh = *(RowSh*)shbuf;
    int bi = bid - NB_LAT;        // 0..511
    int p  = bi & 127;
    int bq = bi >> 7;             // 0..3 -> b = bq*8 + r

    // load xv while waiting is fine (doesn't depend on g_lat)
    #pragma unroll
    for (int r = 0; r < 8; r++)
        sh.xv[r][t] = x[(size_t)(bq * 8 + r) * (Cc * Pp) + t * Pp + p];

    // wait for all lat blocks (dispatched first — lowest bids — so no deadlock)
    if (t == 0) {
        while (atomicAdd(&g_sync, 0) < NB_LAT) __nanosleep(128);
    }
    __syncthreads();
    __threadfence();   // acquire: g_lat writes visible

    // anchors linear + LN (8 rows) — float4 smem reads (broadcast LDS.128)
    {
        const float4* wrow4 = (const float4*)(aw + t * Cc);
        float s[8];
        #pragma unroll
        for (int r = 0; r < 8; r++) s[r] = ab[t];
        #pragma unroll 4
        for (int c4 = 0; c4 < Cc / 4; c4++) {
            float4 w = wrow4[c4];
            #pragma unroll
            for (int r = 0; r < 8; r++) {
                float4 xr = *(const float4*)&sh.xv[r][c4 * 4];
                s[r] += xr.x * w.x + xr.y * w.y + xr.z * w.z + xr.w * w.w;
            }
        }
        float v[8];
        #pragma unroll
        for (int r = 0; r < 8; r++) v[r] = s[r];
        redsumN<8>(v, sh.red, t);
        float d8[8];
        #pragma unroll
        for (int r = 0; r < 8; r++) {
            d8[r] = s[r] - v[r] * (1.f / 128.f);
            v[r] = d8[r] * d8[r];
        }
        redsumN<8>(v, sh.red, t);
        #pragma unroll
        for (int r = 0; r < 8; r++)
            sh.av[r][t] = d8[r] * rsqrtf(v[r] * (1.f / 128.f) + EPSV);
    }

    // blank dots (8 rows)
    float lgb[8];
    {
        float bl = blankl[(p & 1) * Cc + t];
        float v[8];
        #pragma unroll
        for (int r = 0; r < 8; r++) v[r] = sh.xv[r][t] * bl;
        redsumN<8>(v, sh.red, t);
        #pragma unroll
        for (int r = 0; r < 8; r++) lgb[r] = v[r] * INV_NORM;
    }
    __syncthreads();   // av visible

    // logits: thread handles k = t + 128*j for all 8 rows
    // float4 smem reads on av (broadcast LDS.128) — 4x fewer LDS instructions
    #pragma unroll
    for (int j = 0; j < 4; j++) {
        int k = t + (j << 7);
        if (k < Kk) {
            const float4* lr = (const float4*)(g_lat + k * Zz);
            float acc[8] = {0.f, 0.f, 0.f, 0.f, 0.f, 0.f, 0.f, 0.f};
            #pragma unroll 4
            for (int i = 0; i < 32; i++) {
                float4 q = lr[i];
                #pragma unroll
                for (int r = 0; r < 8; r++) {
                    float4 a4 = *(const float4*)&sh.av[r][4 * i];
                    acc[r] += q.x * a4.x + q.y * a4.y + q.z * a4.z + q.w * a4.w;
                }
            }
            #pragma unroll
            for (int r = 0; r < 8; r++) sh.lg[r][k] = acc[r] * INV_NORM;
        } else {
            #pragma unroll
            for (int r = 0; r < 8; r++) sh.lg[r][k] = lgb[r];
        }
    }
    __syncthreads();

    // softmax over 512, 8 rows
    float v[8];
    #pragma unroll
    for (int r = 0; r < 8; r++) {
        float m = -1e30f;
        #pragma unroll
        for (int j = 0; j < 4; j++) m = fmaxf(m, sh.lg[r][t + (j << 7)]);
        v[r] = m;
    }
    redmaxN<8>(v, sh.red, t);
    float mx[8];
    #pragma unroll
    for (int r = 0; r < 8; r++) mx[r] = v[r];

    float ev[8][4];
    #pragma unroll
    for (int r = 0; r < 8; r++) {
        float s = 0.f;
        #pragma unroll
        for (int j = 0; j < 4; j++) {
            ev[r][j] = expf(sh.lg[r][t + (j << 7)] - mx[r]);
            s += ev[r][j];
        }
        v[r] = s;
    }
    redsumN<8>(v, sh.red, t);

    #pragma unroll
    for (int r = 0; r < 8; r++) {
        int b = bq * 8 + r;
        int n = (b << 7) + p;
        int m = (p << 5) + b;
        float inv_sum = 1.0f / v[r];
        float lse = mx[r] + logf(v[r]);
        float* out_w  = out + OFF_W  + (size_t)n * KL;
        float* out_l  = out + OFF_L  + (size_t)n * KL;
        float* out_lp = out + OFF_LP + (size_t)m * KL;
        __half* wa = g_wA + (size_t)m * KP;
        #pragma unroll
        for (int j = 0; j < 4; j++) {
            int k = t + (j << 7);
            float l = sh.lg[r][k];
            float w = ev[r][j] * inv_sum;
            out_w[k]  = w;
            out_l[k]  = l;
            out_lp[k] = l - lse;
            wa[k] = __float2half(w);
        }
    }
}

// ---------------------------------------------------------------------------
// Kernel 4: mma.sync fp16 GEMM  C[4096,16384] = A[4096,512] @ B[16384,512]^T
// CTA 128x128x32, 8 warps, 3-stage cp.async pipeline, 2 CTAs/SM  (round-10)
// ---------------------------------------------------------------------------
__global__ void __launch_bounds__(256, 2) k_gemm(float* __restrict__ outS) {
    extern __shared__ __align__(128) char sm[];   // STAGES x [A|B]

    // reset the fused-kernel sync counter for the next graph replay
    if (blockIdx.x == 0 && blockIdx.y == 0 && threadIdx.x == 0) g_sync = 0;

    int t = threadIdx.x;
    int lane = t & 31;
    int wid = t >> 5;
    int warp_m = wid & 3;          // 32-row slice
    int warp_n = wid >> 2;         // 64-col slice
    int n0 = blockIdx.x * TN;
    int m0 = blockIdx.y * TM;

    uint32_t smb = smem_u32(sm);

    // cp.async mapping: thread covers rows qr0 and qr0+64, 16B chunk qc
    int qr0 = t >> 2, qc = t & 3;
    int qr1 = qr0 + 64;

    const char* gA0 = (const char*)g_wA  + (size_t)(m0 + qr0) * (KP * 2) + qc * 16;
    const char* gA1 = (const char*)g_wA  + (size_t)(m0 + qr1) * (KP * 2) + qc * 16;
    const char* gB0 = (const char*)g_spT + (size_t)(n0 + qr0) * (KP * 2) + qc * 16;
    const char* gB1 = (const char*)g_spT + (size_t)(n0 + qr1) * (KP * 2) + qc * 16;

    uint32_t sA0 = smb + qr0 * RP + qc * 16;
    uint32_t sA1 = smb + qr1 * RP + qc * 16;
    uint32_t sB0 = sA0 + TILE_BYTES;
    uint32_t sB1 = sA1 + TILE_BYTES;

    uint32_t lmA = smb + (warp_m * 32 + (lane & 15)) * RP + (lane >> 4) * 16;
    uint32_t lmB = smb + TILE_BYTES
                 + (warp_n * 64 + (lane & 7) + ((lane >> 4) & 1) * 8) * RP
                 + ((lane >> 3) & 1) * 16;

    float acc[2][8][4];
    #pragma unroll
    for (int mt = 0; mt < 2; mt++)
        #pragma unroll
        for (int nt = 0; nt < 8; nt++)
            #pragma unroll
            for (int q = 0; q < 4; q++) acc[mt][nt][q] = 0.f;

    // prefetch chunks 0,1 into stages 0,1
    #pragma unroll
    for (int s = 0; s < STAGES - 1; s++) {
        uint32_t so = s * STAGE_BYTES;
        int cb = s * 64;
        CP_ASYNC16(sA0 + so, gA0 + cb);
        CP_ASYNC16(sA1 + so, gA1 + cb);
        CP_ASYNC16(sB0 + so, gB0 + cb);
        CP_ASYNC16(sB1 + so, gB1 + cb);
        CP_COMMIT();
    }

    for (int c = 0; c < NCHUNK; c++) {
        CP_WAIT1();            // chunk c landed
        __syncthreads();       // all warps past compute of c-1 -> stage reuse safe

        // issue chunk c+2 into stage (c+2)%STAGES; always commit (group count)
        int cn = c + STAGES - 1;
        if (cn < NCHUNK) {
            uint32_t so = (cn % STAGES) * STAGE_BYTES;
            int cb = cn * 64;
            CP_ASYNC16(sA0 + so, gA0 + cb);
            CP_ASYNC16(sA1 + so, gA1 + cb);
            CP_ASYNC16(sB0 + so, gB0 + cb);
            CP_ASYNC16(sB1 + so, gB1 + cb);
        }
        CP_COMMIT();

        uint32_t aoff = lmA + (c % STAGES) * STAGE_BYTES;
        uint32_t boff = lmB + (c % STAGES) * STAGE_BYTES;
        #pragma unroll
        for (int kt = 0; kt < 2; kt++) {
            uint32_t a[2][4];
            #pragma unroll
            for (int mt = 0; mt < 2; mt++)
                LDSM4(a[mt][0], a[mt][1], a[mt][2], a[mt][3],
                      aoff + mt * (16 * RP) + kt * 32);
            uint32_t bfr[8][2];
            #pragma unroll
            for (int pg = 0; pg < 4; pg++)
                LDSM4(bfr[2 * pg][0], bfr[2 * pg][1],
                      bfr[2 * pg + 1][0], bfr[2 * pg + 1][1],
                      boff + pg * (16 * RP) + kt * 32);
            #pragma unroll
            for (int mt = 0; mt < 2; mt++)
                #pragma unroll
                for (int nt = 0; nt < 8; nt++)
                    mma16816(acc[mt][nt], a[mt], bfr[nt]);
        }
    }

    // epilogue
    int rbase = m0 + warp_m * 32 + (lane >> 2);
    int cbase = n0 + warp_n * 64 + (lane & 3) * 2;
    #pragma unroll
    for (int mt = 0; mt < 2; mt++) {
        #pragma unroll
        for (int nt = 0; nt < 8; nt++) {
            int r = rbase + mt * 16;
            int cc = cbase + nt * 8;
            *(float2*)(outS + (size_t)r * Ntot + cc) =
                make_float2(acc[mt][nt][0], acc[mt][nt][1]);
            *(float2*)(outS + (size_t)(r + 8) * Ntot + cc) =
                make_float2(acc[mt][nt][2], acc[mt][nt][3]);
        }
    }
}

// ---------------------------------------------------------------------------
// Launch
// ---------------------------------------------------------------------------
extern "C" void kernel_launch(void* const* d_in, const int* in_sizes, int n_in,
                              void* d_out, int out_size) {
    const float* x       = (const float*)d_in[0];
    const float* latents = (const float*)d_in[1];
    const float* blankl  = (const float*)d_in[2];
    const float* lw      = (const float*)d_in[3];
    const float* lb      = (const float*)d_in[4];
    const float* aw      = (const float*)d_in[5];
    const float* ab      = (const float*)d_in[6];
    const float* proto   = (const float*)d_in[7];
    const float* masks   = (const float*)d_in[8];
    float* out = (float*)d_out;

    static int smem_set = 0;
    if (!smem_set) {
        cudaFuncSetAttribute(k_gemm, cudaFuncAttributeMaxDynamicSharedMemorySize,
                             SMEM_DYN);
        smem_set = 1;
    }

    // launch 1: lat (0..127) + row (128..639, waits on lat) + prep (640..2687)
    k_fused<<<NB_LAT + NB_ROW + NB_PREP, 128>>>(
        latents, lw, lb, x, blankl, aw, ab, proto, masks, out);
    // launch 2: tensor-core GEMM (needs g_wA, g_spT); also resets g_sync
    dim3 gg(Ntot / TN, Nn / TM);
    k_gemm<<<gg, 256, SMEM_DYN>>>(out + OFF_S);
}

// round 16
// speedup vs baseline: 1.3088x; 1.0439x over previous
#include <cuda_runtime.h>
#include <cuda_fp16.h>
#include <math.h>
#include <stdint.h>

// ---------------------------------------------------------------------------
// Problem constants
// ---------------------------------------------------------------------------
#define Bb   32
#define Cc   128
#define Pp   128
#define Nn   (Bb * Pp)    // 4096 rows
#define Kk   510
#define KL   512
#define Zz   128
#define DS   256
#define HW   4096
#define EPSV 1e-5f
#define INV_NORM 0.08838834764831845f

#define KP   512
#define Ntot 16384        // 4*HW

// output layout
#define OFF_W   0
#define OFF_L   (Nn * KL)
#define OFF_LP  (2 * Nn * KL)
#define OFF_S   (3 * Nn * KL)

// GEMM tiling: CTA 128x128x32, 3-stage cp.async pipeline (round-10 proven)
#define TM 128
#define TN 128
#define TK 32                 // fp16 per k-chunk (64 B per row)
#define NCHUNK (KP / TK)      // 16
#define RP 80                 // smem row pitch (64B data + 16B pad)
#define TILE_BYTES (128 * RP) // 10240
#define STAGE_BYTES (2 * TILE_BYTES)
#define STAGES 3
#define SMEM_DYN (STAGES * STAGE_BYTES)   // 61440

// fused launch-1 block ranges: lat -> prep -> row (row LAST so it never
// occupies wave-1 slots spinning; lat is dispatched first of all)
#define NB_LAT  128
#define NB_PREP 2048
#define NB_ROW  512
#define BID_PREP (NB_LAT)
#define BID_ROW  (NB_LAT + NB_PREP)

// ---------------------------------------------------------------------------
// Device scratch (zero-initialized; rows k>=510 of g_spT stay zero)
// ---------------------------------------------------------------------------
__device__ __align__(16) float  g_lat[Kk * Zz];
__device__ __align__(16) __half g_wA [Nn * KP];            // 4.2 MB
__device__ __align__(16) __half g_spT[(size_t)Ntot * KP];  // 16.8 MB
__device__ int g_sync = 0;                                  // lat-done counter

// ---------------------------------------------------------------------------
// PTX helpers (sm_80-era; valid on plain compute_103 target)
// ---------------------------------------------------------------------------
__device__ __forceinline__ uint32_t smem_u32(const void* p) {
    uint32_t a;
    asm("{ .reg .u64 t; cvta.to.shared.u64 t, %1; cvt.u32.u64 %0, t; }"
        : "=r"(a) : "l"(p));
    return a;
}
#define CP_ASYNC16(dst, src) \
    asm volatile("cp.async.cg.shared.global [%0], [%1], 16;" :: "r"(dst), "l"(src))
#define CP_COMMIT() asm volatile("cp.async.commit_group;" ::: "memory")
#define CP_WAIT1()  asm volatile("cp.async.wait_group 1;" ::: "memory")

#define LDSM4(r0, r1, r2, r3, addr) \
    asm volatile("ldmatrix.sync.aligned.m8n8.x4.shared.b16 {%0,%1,%2,%3}, [%4];" \
        : "=r"(r0), "=r"(r1), "=r"(r2), "=r"(r3) : "r"(addr))

__device__ __forceinline__ void mma16816(float* c, const uint32_t* a,
                                         const uint32_t* b) {
    asm volatile(
        "mma.sync.aligned.m16n8k16.row.col.f32.f16.f16.f32 "
        "{%0,%1,%2,%3}, {%4,%5,%6,%7}, {%8,%9}, {%0,%1,%2,%3};"
        : "+f"(c[0]), "+f"(c[1]), "+f"(c[2]), "+f"(c[3])
        : "r"(a[0]), "r"(a[1]), "r"(a[2]), "r"(a[3]), "r"(b[0]), "r"(b[1]));
}

// ---------------------------------------------------------------------------
// R-row block reductions over 128 threads
// ---------------------------------------------------------------------------
template <int R>
__device__ __forceinline__ void redsumN(float v[R], float red[4][R], int t) {
    #pragma unroll
    for (int o = 16; o; o >>= 1)
        #pragma unroll
        for (int r = 0; r < R; r++) v[r] += __shfl_down_sync(0xffffffffu, v[r], o);
    if ((t & 31) == 0)
        #pragma unroll
        for (int r = 0; r < R; r++) red[t >> 5][r] = v[r];
    __syncthreads();
    #pragma unroll
    for (int r = 0; r < R; r++)
        v[r] = red[0][r] + red[1][r] + red[2][r] + red[3][r];
    __syncthreads();
}
template <int R>
__device__ __forceinline__ void redmaxN(float v[R], float red[4][R], int t) {
    #pragma unroll
    for (int o = 16; o; o >>= 1)
        #pragma unroll
        for (int r = 0; r < R; r++)
            v[r] = fmaxf(v[r], __shfl_down_sync(0xffffffffu, v[r], o));
    if ((t & 31) == 0)
        #pragma unroll
        for (int r = 0; r < R; r++) red[t >> 5][r] = v[r];
    __syncthreads();
    #pragma unroll
    for (int r = 0; r < R; r++)
        v[r] = fmaxf(fmaxf(red[0][r], red[1][r]), fmaxf(red[2][r], red[3][r]));
    __syncthreads();
}

// ---------------------------------------------------------------------------
// Shared-memory overlays for the fused kernel (lat | prep | row)
// ---------------------------------------------------------------------------
struct LatSh {
    float lv[4][DS];       // 4 KB
    float lws[128][33];    // 16.9 KB staged lw tile
    float red[4][4];
};
struct RowSh {
    float xv[8][Cc];
    float av[8][Zz];
    float lg[8][KL];
    float red[4][8];
};
struct PrepSh { float tile[64][65]; };

#define MAXSH(a, b) ((a) > (b) ? (a) : (b))
#define SHBYTES MAXSH(sizeof(LatSh), MAXSH(sizeof(RowSh), sizeof(PrepSh)))

// ---------------------------------------------------------------------------
// Fused launch 1:
//   bids [0, 128)        -> k_lat (4 latents each; signals g_sync)
//   bids [128, 2176)     -> k_prep (independent; fills wave 1 behind lat)
//   bids [2176, 2688)    -> k_row (spins on g_sync == NB_LAT; dispatched last)
// ---------------------------------------------------------------------------
__global__ void __launch_bounds__(128) k_fused(
        const float* __restrict__ latents,
        const float* __restrict__ lw,
        const float* __restrict__ lb,
        const float* __restrict__ x,
        const float* __restrict__ blankl,
        const float* __restrict__ aw,
        const float* __restrict__ ab,
        const float* __restrict__ proto,
        const float* __restrict__ masks,
        float* __restrict__ out) {
    __shared__ __align__(16) char shbuf[SHBYTES];
    int t = threadIdx.x;
    int bid = blockIdx.x;

    if (bid < NB_LAT) {
        // ================= k_lat: 4 latents per block ======================
        LatSh& sh = *(LatSh*)shbuf;
        int k0 = bid * 4;

        #pragma unroll
        for (int r = 0; r < 4; r++) {
            int k = k0 + r;
            float a = 0.f, b2 = 0.f;
            if (k < Kk) { a = latents[k * DS + t]; b2 = latents[k * DS + t + 128]; }
            sh.lv[r][t] = a; sh.lv[r][t + 128] = b2;
        }
        __syncthreads();

        float s[4] = {lb[t], lb[t], lb[t], lb[t]};
        for (int dt = 0; dt < 8; dt++) {
            int d0 = dt * 32;
            #pragma unroll
            for (int i = 0; i < 32; i++) {
                int idx = i * 128 + t;
                int z = idx >> 5, dd = idx & 31;
                sh.lws[z][dd] = lw[z * DS + d0 + dd];
            }
            __syncthreads();
            #pragma unroll 8
            for (int dd = 0; dd < 32; dd++) {
                float w = sh.lws[t][dd];
                #pragma unroll
                for (int r = 0; r < 4; r++) s[r] += sh.lv[r][d0 + dd] * w;
            }
            __syncthreads();
        }

        float v[4];
        #pragma unroll
        for (int r = 0; r < 4; r++) v[r] = s[r];
        redsumN<4>(v, sh.red, t);
        float d4[4];
        #pragma unroll
        for (int r = 0; r < 4; r++) {
            d4[r] = s[r] - v[r] * (1.f / 128.f);
            v[r] = d4[r] * d4[r];
        }
        redsumN<4>(v, sh.red, t);
        #pragma unroll
        for (int r = 0; r < 4; r++) {
            int k = k0 + r;
            if (k < Kk)
                g_lat[k * Zz + t] = d4[r] * rsqrtf(v[r] * (1.f / 128.f) + EPSV);
        }
        __threadfence();
        __syncthreads();
        if (t == 0) atomicAdd(&g_sync, 1);
        return;
    }

    if (bid < BID_ROW) {
        // ================= k_prep: sprite^T fp16 (vectorized) ==============
        PrepSh& sh = *(PrepSh*)shbuf;
        int bi = bid - BID_PREP;           // 0..2047
        int n0 = (bi & 255) * 64;          // Ntot/64 = 256
        int k0 = (bi >> 8) * 64;           // KP/64 = 8

        // read: 64 rows x 64 cols, float4 global loads (16 n-cols per item)
        // 1024 items of 4 floats
        for (int idx = t; idx < 1024; idx += 128) {
            int kk = idx >> 4;             // 0..63
            int nn = (idx & 15) * 4;       // 0..60
            int k = k0 + kk, n = n0 + nn;
            int ch = n >> 12, i = n & 4095;
            float4 s = make_float4(0.f, 0.f, 0.f, 0.f);
            if (k < Kk) {
                const float* src = (ch < 3)
                    ? proto + (size_t)k * (3 * HW) + ch * HW + i
                    : masks + (size_t)k * HW + i;
                s = *(const float4*)src;
            }
            sh.tile[kk][nn]     = s.x;
            sh.tile[kk][nn + 1] = s.y;
            sh.tile[kk][nn + 2] = s.z;
            sh.tile[kk][nn + 3] = s.w;
        }
        __syncthreads();

        // write: transpose out as 8-byte packed half2 pairs (4 kk per item)
        for (int idx = t; idx < 1024; idx += 128) {
            int nn = idx >> 4;             // 0..63
            int kk = (idx & 15) * 4;       // 0..60
            if (k0 + kk < Kk) {            // k0+kk multiple of 4; Kk=510>508 ok
                __half2 h01 = __floats2half2_rn(sh.tile[kk][nn],
                                                sh.tile[kk + 1][nn]);
                // zero elements beyond Kk (k = 510, 511)
                float f2 = (k0 + kk + 2 < Kk) ? sh.tile[kk + 2][nn] : 0.f;
                float f3 = (k0 + kk + 3 < Kk) ? sh.tile[kk + 3][nn] : 0.f;
                __half2 h23 = __floats2half2_rn(f2, f3);
                __half2* dst = (__half2*)(g_spT + (size_t)(n0 + nn) * KP
                                          + k0 + kk);
                dst[0] = h01;
                dst[1] = h23;
            }
        }
        return;
    }

    // ================= k_row: 8 rows per block =============================
    RowSh& sh = *(RowSh*)shbuf;
    int bi = bid - BID_ROW;       // 0..511
    int p  = bi & 127;
    int bq = bi >> 7;             // 0..3 -> b = bq*8 + r

    // load xv while waiting is fine (doesn't depend on g_lat)
    #pragma unroll
    for (int r = 0; r < 8; r++)
        sh.xv[r][t] = x[(size_t)(bq * 8 + r) * (Cc * Pp) + t * Pp + p];

    // wait for all lat blocks (dispatched first — lowest bids — no deadlock)
    if (t == 0) {
        while (atomicAdd(&g_sync, 0) < NB_LAT) __nanosleep(128);
    }
    __syncthreads();
    __threadfence();   // acquire: g_lat writes visible

    // anchors linear + LN (8 rows) — float4 smem reads
    {
        const float4* wrow4 = (const float4*)(aw + t * Cc);
        float s[8];
        #pragma unroll
        for (int r = 0; r < 8; r++) s[r] = ab[t];
        #pragma unroll 4
        for (int c4 = 0; c4 < Cc / 4; c4++) {
            float4 w = wrow4[c4];
            #pragma unroll
            for (int r = 0; r < 8; r++) {
                float4 xr = *(const float4*)&sh.xv[r][c4 * 4];
                s[r] += xr.x * w.x + xr.y * w.y + xr.z * w.z + xr.w * w.w;
            }
        }
        float v[8];
        #pragma unroll
        for (int r = 0; r < 8; r++) v[r] = s[r];
        redsumN<8>(v, sh.red, t);
        float d8[8];
        #pragma unroll
        for (int r = 0; r < 8; r++) {
            d8[r] = s[r] - v[r] * (1.f / 128.f);
            v[r] = d8[r] * d8[r];
        }
        redsumN<8>(v, sh.red, t);
        #pragma unroll
        for (int r = 0; r < 8; r++)
            sh.av[r][t] = d8[r] * rsqrtf(v[r] * (1.f / 128.f) + EPSV);
    }

    // blank dots (8 rows)
    float lgb[8];
    {
        float bl = blankl[(p & 1) * Cc + t];
        float v[8];
        #pragma unroll
        for (int r = 0; r < 8; r++) v[r] = sh.xv[r][t] * bl;
        redsumN<8>(v, sh.red, t);
        #pragma unroll
        for (int r = 0; r < 8; r++) lgb[r] = v[r] * INV_NORM;
    }
    __syncthreads();   // av visible

    // logits: thread handles k = t + 128*j for all 8 rows (float4 LDS)
    #pragma unroll
    for (int j = 0; j < 4; j++) {
        int k = t + (j << 7);
        if (k < Kk) {
            const float4* lr = (const float4*)(g_lat + k * Zz);
            float acc[8] = {0.f, 0.f, 0.f, 0.f, 0.f, 0.f, 0.f, 0.f};
            #pragma unroll 4
            for (int i = 0; i < 32; i++) {
                float4 q = lr[i];
                #pragma unroll
                for (int r = 0; r < 8; r++) {
                    float4 a4 = *(const float4*)&sh.av[r][4 * i];
                    acc[r] += q.x * a4.x + q.y * a4.y + q.z * a4.z + q.w * a4.w;
                }
            }
            #pragma unroll
            for (int r = 0; r < 8; r++) sh.lg[r][k] = acc[r] * INV_NORM;
        } else {
            #pragma unroll
            for (int r = 0; r < 8; r++) sh.lg[r][k] = lgb[r];
        }
    }
    __syncthreads();

    // softmax over 512, 8 rows
    float v[8];
    #pragma unroll
    for (int r = 0; r < 8; r++) {
        float m = -1e30f;
        #pragma unroll
        for (int j = 0; j < 4; j++) m = fmaxf(m, sh.lg[r][t + (j << 7)]);
        v[r] = m;
    }
    redmaxN<8>(v, sh.red, t);
    float mx[8];
    #pragma unroll
    for (int r = 0; r < 8; r++) mx[r] = v[r];

    float ev[8][4];
    #pragma unroll
    for (int r = 0; r < 8; r++) {
        float s = 0.f;
        #pragma unroll
        for (int j = 0; j < 4; j++) {
            ev[r][j] = expf(sh.lg[r][t + (j << 7)] - mx[r]);
            s += ev[r][j];
        }
        v[r] = s;
    }
    redsumN<8>(v, sh.red, t);

    #pragma unroll
    for (int r = 0; r < 8; r++) {
        int b = bq * 8 + r;
        int n = (b << 7) + p;
        int m = (p << 5) + b;
        float inv_sum = 1.0f / v[r];
        float lse = mx[r] + logf(v[r]);
        float* out_w  = out + OFF_W  + (size_t)n * KL;
        float* out_l  = out + OFF_L  + (size_t)n * KL;
        float* out_lp = out + OFF_LP + (size_t)m * KL;
        __half* wa = g_wA + (size_t)m * KP;
        #pragma unroll
        for (int j = 0; j < 4; j++) {
            int k = t + (j << 7);
            float l = sh.lg[r][k];
            float w = ev[r][j] * inv_sum;
            out_w[k]  = w;
            out_l[k]  = l;
            out_lp[k] = l - lse;
            wa[k] = __float2half(w);
        }
    }
}

// ---------------------------------------------------------------------------
// Kernel 4: mma.sync fp16 GEMM  C[4096,16384] = A[4096,512] @ B[16384,512]^T
// CTA 128x128x32, 8 warps, 3-stage cp.async pipeline, 2 CTAs/SM  (round-10)
// ---------------------------------------------------------------------------
__global__ void __launch_bounds__(256, 2) k_gemm(float* __restrict__ outS) {
    extern __shared__ __align__(128) char sm[];   // STAGES x [A|B]

    // reset the fused-kernel sync counter for the next graph replay
    if (blockIdx.x == 0 && blockIdx.y == 0 && threadIdx.x == 0) g_sync = 0;

    int t = threadIdx.x;
    int lane = t & 31;
    int wid = t >> 5;
    int warp_m = wid & 3;          // 32-row slice
    int warp_n = wid >> 2;         // 64-col slice
    int n0 = blockIdx.x * TN;
    int m0 = blockIdx.y * TM;

    uint32_t smb = smem_u32(sm);

    // cp.async mapping: thread covers rows qr0 and qr0+64, 16B chunk qc
    int qr0 = t >> 2, qc = t & 3;
    int qr1 = qr0 + 64;

    const char* gA0 = (const char*)g_wA  + (size_t)(m0 + qr0) * (KP * 2) + qc * 16;
    const char* gA1 = (const char*)g_wA  + (size_t)(m0 + qr1) * (KP * 2) + qc * 16;
    const char* gB0 = (const char*)g_spT + (size_t)(n0 + qr0) * (KP * 2) + qc * 16;
    const char* gB1 = (const char*)g_spT + (size_t)(n0 + qr1) * (KP * 2) + qc * 16;

    uint32_t sA0 = smb + qr0 * RP + qc * 16;
    uint32_t sA1 = smb + qr1 * RP + qc * 16;
    uint32_t sB0 = sA0 + TILE_BYTES;
    uint32_t sB1 = sA1 + TILE_BYTES;

    uint32_t lmA = smb + (warp_m * 32 + (lane & 15)) * RP + (lane >> 4) * 16;
    uint32_t lmB = smb + TILE_BYTES
                 + (warp_n * 64 + (lane & 7) + ((lane >> 4) & 1) * 8) * RP
                 + ((lane >> 3) & 1) * 16;

    float acc[2][8][4];
    #pragma unroll
    for (int mt = 0; mt < 2; mt++)
        #pragma unroll
        for (int nt = 0; nt < 8; nt++)
            #pragma unroll
            for (int q = 0; q < 4; q++) acc[mt][nt][q] = 0.f;

    // prefetch chunks 0,1 into stages 0,1
    #pragma unroll
    for (int s = 0; s < STAGES - 1; s++) {
        uint32_t so = s * STAGE_BYTES;
        int cb = s * 64;
        CP_ASYNC16(sA0 + so, gA0 + cb);
        CP_ASYNC16(sA1 + so, gA1 + cb);
        CP_ASYNC16(sB0 + so, gB0 + cb);
        CP_ASYNC16(sB1 + so, gB1 + cb);
        CP_COMMIT();
    }

    for (int c = 0; c < NCHUNK; c++) {
        CP_WAIT1();            // chunk c landed
        __syncthreads();       // all warps past compute of c-1 -> stage reuse safe

        // issue chunk c+2 into stage (c+2)%STAGES; always commit (group count)
        int cn = c + STAGES - 1;
        if (cn < NCHUNK) {
            uint32_t so = (cn % STAGES) * STAGE_BYTES;
            int cb = cn * 64;
            CP_ASYNC16(sA0 + so, gA0 + cb);
            CP_ASYNC16(sA1 + so, gA1 + cb);
            CP_ASYNC16(sB0 + so, gB0 + cb);
            CP_ASYNC16(sB1 + so, gB1 + cb);
        }
        CP_COMMIT();

        uint32_t aoff = lmA + (c % STAGES) * STAGE_BYTES;
        uint32_t boff = lmB + (c % STAGES) * STAGE_BYTES;
        #pragma unroll
        for (int kt = 0; kt < 2; kt++) {
            uint32_t a[2][4];
            #pragma unroll
            for (int mt = 0; mt < 2; mt++)
                LDSM4(a[mt][0], a[mt][1], a[mt][2], a[mt][3],
                      aoff + mt * (16 * RP) + kt * 32);
            uint32_t bfr[8][2];
            #pragma unroll
            for (int pg = 0; pg < 4; pg++)
                LDSM4(bfr[2 * pg][0], bfr[2 * pg][1],
                      bfr[2 * pg + 1][0], bfr[2 * pg + 1][1],
                      boff + pg * (16 * RP) + kt * 32);
            #pragma unroll
            for (int mt = 0; mt < 2; mt++)
                #pragma unroll
                for (int nt = 0; nt < 8; nt++)
                    mma16816(acc[mt][nt], a[mt], bfr[nt]);
        }
    }

    // epilogue
    int rbase = m0 + warp_m * 32 + (lane >> 2);
    int cbase = n0 + warp_n * 64 + (lane & 3) * 2;
    #pragma unroll
    for (int mt = 0; mt < 2; mt++) {
        #pragma unroll
        for (int nt = 0; nt < 8; nt++) {
            int r = rbase + mt * 16;
            int cc = cbase + nt * 8;
            *(float2*)(outS + (size_t)r * Ntot + cc) =
                make_float2(acc[mt][nt][0], acc[mt][nt][1]);
            *(float2*)(outS + (size_t)(r + 8) * Ntot + cc) =
                make_float2(acc[mt][nt][2], acc[mt][nt][3]);
        }
    }
}

// ---------------------------------------------------------------------------
// Launch
// ---------------------------------------------------------------------------
extern "C" void kernel_launch(void* const* d_in, const int* in_sizes, int n_in,
                              void* d_out, int out_size) {
    const float* x       = (const float*)d_in[0];
    const float* latents = (const float*)d_in[1];
    const float* blankl  = (const float*)d_in[2];
    const float* lw      = (const float*)d_in[3];
    const float* lb      = (const float*)d_in[4];
    const float* aw      = (const float*)d_in[5];
    const float* ab      = (const float*)d_in[6];
    const float* proto   = (const float*)d_in[7];
    const float* masks   = (const float*)d_in[8];
    float* out = (float*)d_out;

    static int smem_set = 0;
    if (!smem_set) {
        cudaFuncSetAttribute(k_gemm, cudaFuncAttributeMaxDynamicSharedMemorySize,
                             SMEM_DYN);
        smem_set = 1;
    }

    // launch 1: lat (0..127) + prep (128..2175) + row (2176..2687, waits on lat)
    k_fused<<<NB_LAT + NB_PREP + NB_ROW, 128>>>(
        latents, lw, lb, x, blankl, aw, ab, proto, masks, out);
    // launch 2: tensor-core GEMM (needs g_wA, g_spT); also resets g_sync
    dim3 gg(Ntot / TN, Nn / TM);
    k_gemm<<<gg, 256, SMEM_DYN>>>(out + OFF_S);
}